// round 6
// baseline (speedup 1.0000x reference)
#include <cuda_runtime.h>
#include <cuda_fp16.h>
#include <math.h>

// Problem dims (fixed by the dataset)
#define NMAX   80000
#define N1MAX  40000
#define N2MAX  20000
#define EMAX   1280000
#define NUMK   27
#define BGRAPH 16

// ---------------- scratch (static __device__ — no allocations) ----------------
// fp16 xW2 table, padded: 32 corner-slots (27 used) x 16 halves = 512 halves = 1024B per node
__device__ __align__(16) __half d_xw2h[(size_t)N1MAX * 512];   // 41 MB
__device__ float d_agg1[NMAX * 8];
__device__ int   d_cnt1[NMAX];
__device__ float d_x1max[N1MAX * 8];
__device__ int   d_batch1[N1MAX];
__device__ float d_agg2[N1MAX * 16];
__device__ int   d_cnt2[N1MAX];
__device__ float d_x2max[N2MAX * 16];
__device__ int   d_batch2[N2MAX];
__device__ float d_gsum[BGRAPH * 16];
__device__ int   d_gcnt[BGRAPH];
__device__ int   d_src2[EMAX];
__device__ int   d_dst2[EMAX];

// ---------------- helpers ----------------
__device__ __forceinline__ float elu1(float v) {
    return v > 0.0f ? v : (expf(v) - 1.0f);
}

__device__ __forceinline__ void atomicMaxFloat(float* addr, float value) {
    if (value >= 0.0f)
        atomicMax((int*)addr, __float_as_int(value));
    else
        atomicMin((unsigned int*)addr, __float_as_uint(value));
}

__device__ __forceinline__ void red_add_v4(float* p, float4 v) {
    asm volatile("red.global.add.v4.f32 [%0], {%1,%2,%3,%4};"
                 :: "l"(p), "f"(v.x), "f"(v.y), "f"(v.z), "f"(v.w) : "memory");
}

__device__ __forceinline__ float4 f4fma(float b, float4 a, float4 acc) {
    acc.x += b * a.x; acc.y += b * a.y; acc.z += b * a.z; acc.w += b * a.w;
    return acc;
}

// degree-1 open B-spline basis on 3-dim pseudo coords, K=3
__device__ __forceinline__ void basis27(float a0, float a1, float a2,
                                        float* bw, int* kk) {
    float v0 = a0 * 2.0f, v1 = a1 * 2.0f, v2 = a2 * 2.0f;
    int i0 = (int)v0; i0 = i0 < 0 ? 0 : (i0 > 1 ? 1 : i0);
    int i1 = (int)v1; i1 = i1 < 0 ? 0 : (i1 > 1 ? 1 : i1);
    int i2 = (int)v2; i2 = i2 < 0 ? 0 : (i2 > 1 ? 1 : i2);
    float f0 = v0 - (float)i0, f1 = v1 - (float)i1, f2 = v2 - (float)i2;
    float g0 = 1.0f - f0, g1 = 1.0f - f1, g2 = 1.0f - f2;
#pragma unroll
    for (int s = 0; s < 8; s++) {
        int b0 = s & 1, b1 = (s >> 1) & 1, b2 = (s >> 2) & 1;
        float w0 = b0 ? f0 : g0;
        float w1 = b1 ? f1 : g1;
        float w2 = b2 ? f2 : g2;
        bw[s] = w0 * w1 * w2;
        kk[s] = (i0 + b0) + 3 * (i1 + b1) + 9 * (i2 + b2);
    }
}

// ---------------- kernels ----------------

__global__ void k_init(int N, int N1, int N2) {
    int tid = blockIdx.x * blockDim.x + threadIdx.x;
    int stride = gridDim.x * blockDim.x;
    float4 zf4 = make_float4(0, 0, 0, 0);
    float4 nf4 = make_float4(-INFINITY, -INFINITY, -INFINITY, -INFINITY);
    for (int i = tid; i < N * 2; i += stride)  ((float4*)d_agg1)[i] = zf4;
    for (int i = tid; i < N / 4; i += stride)  ((int4*)d_cnt1)[i] = make_int4(0, 0, 0, 0);
    for (int i = tid; i < N1 * 2; i += stride) ((float4*)d_x1max)[i] = nf4;
    for (int i = tid; i < N1; i += stride)     d_batch1[i] = -0x7fffffff - 1;
    for (int i = tid; i < N1 * 4; i += stride) ((float4*)d_agg2)[i] = zf4;
    for (int i = tid; i < N1 / 4; i += stride) ((int4*)d_cnt2)[i] = make_int4(0, 0, 0, 0);
    for (int i = tid; i < N2 * 4; i += stride) ((float4*)d_x2max)[i] = nf4;
    for (int i = tid; i < N2; i += stride)     d_batch2[i] = -0x7fffffff - 1;
    for (int i = tid; i < BGRAPH * 16; i += stride) d_gsum[i] = 0.0f;
    for (int i = tid; i < BGRAPH; i += stride) d_gcnt[i] = 0;
}

// level-1 edge kernel + bookkeeping fused:
// msg = x0 * (sum_s b_s W1[k_s,0,:]) + x1 * (sum_s b_s W1[k_s,1,:])
// also: cnt1[dst]++, write coarse endpoints for k_edge2.
__global__ void __launch_bounds__(256) k_edge1(
        const int* __restrict__ ei, const float* __restrict__ attr,
        const float* __restrict__ x, const float* __restrict__ W1,
        const int* __restrict__ cluster1, int E) {
    __shared__ float4 sW[NUMK * 5];  // stride 5 float4 per k: [uLo, uHi, vLo, vHi, pad]
    int t = threadIdx.x;
    if (t < NUMK * 4) {
        int k = t >> 2, j = t & 3;
        sW[k * 5 + j] = ((const float4*)W1)[t];
    }
    __syncthreads();
    int e = blockIdx.x * blockDim.x + t;
    if (e >= E) return;
    int src = ei[e];
    int dst = ei[E + e];
    int s2 = __ldg(&cluster1[src]);
    int d2 = __ldg(&cluster1[dst]);
    d_src2[e] = s2;
    d_dst2[e] = d2;
    atomicAdd(&d_cnt1[dst], 1);
    float a0 = attr[3 * e], a1 = attr[3 * e + 1], a2 = attr[3 * e + 2];
    float bw[8]; int kk[8];
    basis27(a0, a1, a2, bw, kk);
    float4 uL = make_float4(0, 0, 0, 0), uH = uL, vL = uL, vH = uL;
#pragma unroll
    for (int s = 0; s < 8; s++) {
        float b = bw[s];
        const float4* p = &sW[kk[s] * 5];
        uL = f4fma(b, p[0], uL);
        uH = f4fma(b, p[1], uH);
        vL = f4fma(b, p[2], vL);
        vH = f4fma(b, p[3], vH);
    }
    float2 xv = __ldg((const float2*)(x) + src);   // the only random gather: 8B
    float4 mL, mH;
    mL.x = xv.x * uL.x + xv.y * vL.x; mL.y = xv.x * uL.y + xv.y * vL.y;
    mL.z = xv.x * uL.z + xv.y * vL.z; mL.w = xv.x * uL.w + xv.y * vL.w;
    mH.x = xv.x * uH.x + xv.y * vH.x; mH.y = xv.x * uH.y + xv.y * vH.y;
    mH.z = xv.x * uH.z + xv.y * vH.z; mH.w = xv.x * uH.w + xv.y * vH.w;
    float* out = d_agg1 + (size_t)dst * 8;
    red_add_v4(out, mL);
    red_add_v4(out + 4, mH);
}

// level-1 node kernel: mean + root + bias + ELU, then seg_max pooling scatter.
// Also accumulates cnt2[c1] += cnt1[n]  (replaces 1.28M edge atomics with 80K).
__global__ void k_node1(const float* __restrict__ x, const int* __restrict__ batch,
                        const int* __restrict__ cluster1,
                        const float* __restrict__ root1, const float* __restrict__ b1,
                        int N) {
    int n = blockIdx.x * blockDim.x + threadIdx.x;
    if (n >= N) return;
    int c = d_cnt1[n];
    float inv = 1.0f / (float)(c > 1 ? c : 1);
    float x0 = x[2 * n], x1 = x[2 * n + 1];
    int c1 = cluster1[n];
    int bt = batch[n];
    float* xm = d_x1max + (size_t)c1 * 8;
#pragma unroll
    for (int o = 0; o < 8; o++) {
        float h = d_agg1[(size_t)n * 8 + o] * inv + x0 * root1[o] + x1 * root1[8 + o] + b1[o];
        h = elu1(h);
        atomicMaxFloat(&xm[o], h);
    }
    atomicMax(&d_batch1[c1], bt);
    atomicAdd(&d_cnt2[c1], c);
}

// xW2 table in fp16, padded rows: [n][32 corner slots][16 half]
// Grid-stride: W2 staged once per block (320 blocks -> 4.4MB L2 traffic, was 69MB).
// 4 nodes per warp, lane owns an output-channel pair -> half2 stores.
__global__ void __launch_bounds__(128) k_xw2(const float* __restrict__ W2, int N1) {
    __shared__ float sW[NUMK * 128];   // 13.8 KB: [k][c][o]
    int t = threadIdx.x;
    for (int i = t; i < NUMK * 128; i += 128) sW[i] = W2[i];
    __syncthreads();
    int warpId = (blockIdx.x * 128 + t) >> 5;
    int lane = t & 31;
    int j = lane & 7;            // output-channel pair index (o = 2j, 2j+1)
    int sub = lane >> 3;         // node within quad
    int totalWarps = gridDim.x * 4;
    for (int base = warpId * 4; base < N1; base += totalWarps * 4) {
        int node = base + sub;
        if (node < N1) {
            const float* xm = d_x1max + (size_t)node * 8;
            float xv[8];
#pragma unroll
            for (int c = 0; c < 8; c++) {
                float v = xm[c];
                xv[c] = (v == -INFINITY) ? 0.0f : v;   // seg_max empty-cluster fix
            }
            __half* outp = d_xw2h + (size_t)node * 512 + 2 * j;
#pragma unroll
            for (int k = 0; k < NUMK; k++) {
                const float2* w = (const float2*)(sW + k * 128) + j;
                float r0 = 0.0f, r1 = 0.0f;
#pragma unroll
                for (int c = 0; c < 8; c++) {
                    float2 wc = w[c * 8];
                    r0 += xv[c] * wc.x;
                    r1 += xv[c] * wc.y;
                }
                *(__half2*)(outp + k * 16) = __floats2half2_rn(r0, r1);
            }
        }
    }
}

// level-2 edge kernel: 2 lanes per edge, each lane owns 8 output channels.
// Each corner read = one 16B load per lane; lane pair covers one fully-used 32B sector.
__global__ void __launch_bounds__(256) k_edge2(const float* __restrict__ attr, int E) {
    int t = blockIdx.x * blockDim.x + threadIdx.x;
    int e = t >> 1;          // edge index
    int sub = t & 1;         // channel octet
    if (e >= E) return;
    int s2 = d_src2[e];
    int d2 = d_dst2[e];
    float a0 = attr[3 * e], a1 = attr[3 * e + 1], a2 = attr[3 * e + 2];
    float bw[8]; int kk[8];
    basis27(a0, a1, a2, bw, kk);
    const uint4* base = (const uint4*)(d_xw2h + (size_t)s2 * 512) + sub;
    uint4 q[8];
#pragma unroll
    for (int s = 0; s < 8; s++) q[s] = __ldg(base + kk[s] * 2);
    float m[8];
#pragma unroll
    for (int i = 0; i < 8; i++) m[i] = 0.0f;
#pragma unroll
    for (int s = 0; s < 8; s++) {
        float b = bw[s];
        float2 f0 = __half22float2(*(__half2*)&q[s].x);
        float2 f1 = __half22float2(*(__half2*)&q[s].y);
        float2 f2 = __half22float2(*(__half2*)&q[s].z);
        float2 f3 = __half22float2(*(__half2*)&q[s].w);
        m[0] += b * f0.x; m[1] += b * f0.y;
        m[2] += b * f1.x; m[3] += b * f1.y;
        m[4] += b * f2.x; m[5] += b * f2.y;
        m[6] += b * f3.x; m[7] += b * f3.y;
    }
    float* out = d_agg2 + (size_t)d2 * 16 + sub * 8;
    red_add_v4(out,     make_float4(m[0], m[1], m[2], m[3]));
    red_add_v4(out + 4, make_float4(m[4], m[5], m[6], m[7]));
}

// level-2 node kernel: mean + root + bias + ELU, then seg_max pooling scatter
__global__ void k_node2(const int* __restrict__ cluster2,
                        const float* __restrict__ root2, const float* __restrict__ b2,
                        int N1) {
    int n = blockIdx.x * blockDim.x + threadIdx.x;
    if (n >= N1) return;
    int c = d_cnt2[n];
    float inv = 1.0f / (float)(c > 1 ? c : 1);
    float xv[8];
#pragma unroll
    for (int i = 0; i < 8; i++) {
        float t = d_x1max[(size_t)n * 8 + i];
        xv[i] = (t == -INFINITY) ? 0.0f : t;
    }
    int c2 = cluster2[n];
    int b1v = d_batch1[n];
    int bt = b1v > 0 ? b1v : 0;
    float* xm = d_x2max + (size_t)c2 * 16;
#pragma unroll
    for (int o = 0; o < 16; o++) {
        float r = 0.0f;
#pragma unroll
        for (int i = 0; i < 8; i++) r += xv[i] * __ldg(&root2[i * 16 + o]);
        float h = d_agg2[(size_t)n * 16 + o] * inv + r + b2[o];
        h = elu1(h);
        atomicMaxFloat(&xm[o], h);
    }
    atomicMax(&d_batch2[c2], bt);
}

// scatter_mean over graphs
__global__ void k_final(int N2) {
    int n = blockIdx.x * blockDim.x + threadIdx.x;
    if (n >= N2) return;
    int b2v = d_batch2[n];
    int b = b2v > 0 ? b2v : 0;
    float v[16];
#pragma unroll
    for (int i = 0; i < 16; i++) {
        float t = d_x2max[(size_t)n * 16 + i];
        v[i] = (t == -INFINITY) ? 0.0f : t;
    }
    float* g = d_gsum + b * 16;
    red_add_v4(g,      make_float4(v[0], v[1], v[2], v[3]));
    red_add_v4(g + 4,  make_float4(v[4], v[5], v[6], v[7]));
    red_add_v4(g + 8,  make_float4(v[8], v[9], v[10], v[11]));
    red_add_v4(g + 12, make_float4(v[12], v[13], v[14], v[15]));
    atomicAdd(&d_gcnt[b], 1);
}

// B=16 MLP head, single block
__global__ void k_mlp(const float* __restrict__ fc1w, const float* __restrict__ fc1b,
                      const float* __restrict__ fc2w, const float* __restrict__ fc2b,
                      float* __restrict__ out) {
    __shared__ float g[BGRAPH * 16];
    __shared__ float hid[BGRAPH * 64];
    int t = threadIdx.x;  // 256 threads
    if (t < BGRAPH * 16) {
        int b = t >> 4;
        int c = d_gcnt[b];
        g[t] = d_gsum[t] / (float)(c > 1 ? c : 1);
    }
    __syncthreads();
    for (int i = t; i < BGRAPH * 64; i += 256) {
        int b = i >> 6, j = i & 63;
        float s = fc1b[j];
#pragma unroll
        for (int k = 0; k < 16; k++) s += g[b * 16 + k] * fc1w[k * 64 + j];
        hid[i] = elu1(s);
    }
    __syncthreads();
    if (t < BGRAPH) {
        float s = fc2b[0];
#pragma unroll
        for (int j = 0; j < 64; j++) s += hid[t * 64 + j] * fc2w[j];
        out[t] = elu1(s);
    }
}

// ---------------- launch ----------------
extern "C" void kernel_launch(void* const* d_in, const int* in_sizes, int n_in,
                              void* d_out, int out_size) {
    const float* x        = (const float*)d_in[0];
    const int*   ei       = (const int*)d_in[1];
    const float* attr     = (const float*)d_in[2];
    const int*   batch    = (const int*)d_in[3];
    const int*   cluster1 = (const int*)d_in[4];
    const int*   cluster2 = (const int*)d_in[5];
    const float* W1       = (const float*)d_in[6];
    const float* root1    = (const float*)d_in[7];
    const float* b1       = (const float*)d_in[8];
    const float* W2       = (const float*)d_in[9];
    const float* root2    = (const float*)d_in[10];
    const float* b2       = (const float*)d_in[11];
    const float* fc1w     = (const float*)d_in[12];
    const float* fc1b     = (const float*)d_in[13];
    const float* fc2w     = (const float*)d_in[14];
    const float* fc2b     = (const float*)d_in[15];
    float* out = (float*)d_out;

    int N  = in_sizes[0] / 2;
    int E  = in_sizes[1] / 2;
    int N1 = in_sizes[5];      // cluster2 has length N1
    int N2 = N1 / 2;

    const int T = 256;
    k_init<<<512, T>>>(N, N1, N2);
    k_edge1<<<(E + T - 1) / T, T>>>(ei, attr, x, W1, cluster1, E);
    k_node1<<<(N + T - 1) / T, T>>>(x, batch, cluster1, root1, b1, N);
    k_xw2<<<320, 128>>>(W2, N1);
    k_edge2<<<(2 * E + T - 1) / T, T>>>(attr, E);
    k_node2<<<(N1 + T - 1) / T, T>>>(cluster2, root2, b2, N1);
    k_final<<<(N2 + T - 1) / T, T>>>(N2);
    k_mlp<<<1, T>>>(fc1w, fc1b, fc2w, fc2b, out);
}

// round 8
// speedup vs baseline: 1.0945x; 1.0945x over previous
#include <cuda_runtime.h>
#include <cuda_fp16.h>
#include <math.h>

// Problem dims (fixed by the dataset)
#define NMAX   80000
#define N1MAX  40000
#define N2MAX  20000
#define EMAX   1280000
#define NUMK   27
#define BGRAPH 16

// ---------------- scratch (static __device__ — no allocations) ----------------
// fp16 xW2 table, padded: 32 corner-slots (27 used) x 16 halves = 512 halves = 1024B per node
__device__ __align__(16) __half d_xw2h[(size_t)N1MAX * 512];   // 41 MB
__device__ float d_agg1[NMAX * 8];
__device__ int   d_cnt1[NMAX];
__device__ float d_x1max[N1MAX * 8];
__device__ int   d_batch1[N1MAX];
__device__ float d_agg2[N1MAX * 16];
__device__ int   d_cnt2[N1MAX];
__device__ float d_x2max[N2MAX * 16];
__device__ int   d_batch2[N2MAX];
__device__ float d_gsum[BGRAPH * 16];
__device__ int   d_gcnt[BGRAPH];
__device__ int2  d_sd2[EMAX];    // packed (src2, dst2)

// ---------------- helpers ----------------
__device__ __forceinline__ float elu1(float v) {
    return v > 0.0f ? v : (expf(v) - 1.0f);
}

__device__ __forceinline__ void atomicMaxFloat(float* addr, float value) {
    if (value >= 0.0f)
        atomicMax((int*)addr, __float_as_int(value));
    else
        atomicMin((unsigned int*)addr, __float_as_uint(value));
}

__device__ __forceinline__ void red_add_v4(float* p, float4 v) {
    asm volatile("red.global.add.v4.f32 [%0], {%1,%2,%3,%4};"
                 :: "l"(p), "f"(v.x), "f"(v.y), "f"(v.z), "f"(v.w) : "memory");
}

__device__ __forceinline__ float4 f4fma(float b, float4 a, float4 acc) {
    acc.x += b * a.x; acc.y += b * a.y; acc.z += b * a.z; acc.w += b * a.w;
    return acc;
}

// degree-1 open B-spline basis on 3-dim pseudo coords, K=3
__device__ __forceinline__ void basis27(float a0, float a1, float a2,
                                        float* bw, int* kk) {
    float v0 = a0 * 2.0f, v1 = a1 * 2.0f, v2 = a2 * 2.0f;
    int i0 = (int)v0; i0 = i0 < 0 ? 0 : (i0 > 1 ? 1 : i0);
    int i1 = (int)v1; i1 = i1 < 0 ? 0 : (i1 > 1 ? 1 : i1);
    int i2 = (int)v2; i2 = i2 < 0 ? 0 : (i2 > 1 ? 1 : i2);
    float f0 = v0 - (float)i0, f1 = v1 - (float)i1, f2 = v2 - (float)i2;
    float g0 = 1.0f - f0, g1 = 1.0f - f1, g2 = 1.0f - f2;
#pragma unroll
    for (int s = 0; s < 8; s++) {
        int b0 = s & 1, b1 = (s >> 1) & 1, b2 = (s >> 2) & 1;
        float w0 = b0 ? f0 : g0;
        float w1 = b1 ? f1 : g1;
        float w2 = b2 ? f2 : g2;
        bw[s] = w0 * w1 * w2;
        kk[s] = (i0 + b0) + 3 * (i1 + b1) + 9 * (i2 + b2);
    }
}

// ---------------- kernels ----------------

__global__ void k_init(int N, int N1, int N2) {
    int tid = blockIdx.x * blockDim.x + threadIdx.x;
    int stride = gridDim.x * blockDim.x;
    float4 zf4 = make_float4(0, 0, 0, 0);
    float4 nf4 = make_float4(-INFINITY, -INFINITY, -INFINITY, -INFINITY);
    for (int i = tid; i < N * 2; i += stride)  ((float4*)d_agg1)[i] = zf4;
    for (int i = tid; i < N / 4; i += stride)  ((int4*)d_cnt1)[i] = make_int4(0, 0, 0, 0);
    for (int i = tid; i < N1 * 2; i += stride) ((float4*)d_x1max)[i] = nf4;
    for (int i = tid; i < N1; i += stride)     d_batch1[i] = -0x7fffffff - 1;
    for (int i = tid; i < N1 * 4; i += stride) ((float4*)d_agg2)[i] = zf4;
    for (int i = tid; i < N1 / 4; i += stride) ((int4*)d_cnt2)[i] = make_int4(0, 0, 0, 0);
    for (int i = tid; i < N2 * 4; i += stride) ((float4*)d_x2max)[i] = nf4;
    for (int i = tid; i < N2; i += stride)     d_batch2[i] = -0x7fffffff - 1;
    for (int i = tid; i < BGRAPH * 16; i += stride) d_gsum[i] = 0.0f;
    for (int i = tid; i < BGRAPH; i += stride) d_gcnt[i] = 0;
}

// level-1 edge kernel + bookkeeping fused:
// msg = x0 * (sum_s b_s W1[k_s,0,:]) + x1 * (sum_s b_s W1[k_s,1,:])
// also: cnt1[dst]++, write packed coarse endpoints for k_edge2.
__global__ void __launch_bounds__(256) k_edge1(
        const int* __restrict__ ei, const float* __restrict__ attr,
        const float* __restrict__ x, const float* __restrict__ W1,
        const int* __restrict__ cluster1, int E) {
    __shared__ float4 sW[NUMK * 5];  // stride 5 float4 per k: [uLo, uHi, vLo, vHi, pad]
    int t = threadIdx.x;
    if (t < NUMK * 4) {
        int k = t >> 2, j = t & 3;
        sW[k * 5 + j] = ((const float4*)W1)[t];
    }
    __syncthreads();
    int e = blockIdx.x * blockDim.x + t;
    if (e >= E) return;
    int src = ei[e];
    int dst = ei[E + e];
    int s2 = __ldg(&cluster1[src]);
    int d2 = __ldg(&cluster1[dst]);
    d_sd2[e] = make_int2(s2, d2);
    atomicAdd(&d_cnt1[dst], 1);
    float a0 = attr[3 * e], a1 = attr[3 * e + 1], a2 = attr[3 * e + 2];
    float bw[8]; int kk[8];
    basis27(a0, a1, a2, bw, kk);
    float4 uL = make_float4(0, 0, 0, 0), uH = uL, vL = uL, vH = uL;
#pragma unroll
    for (int s = 0; s < 8; s++) {
        float b = bw[s];
        const float4* p = &sW[kk[s] * 5];
        uL = f4fma(b, p[0], uL);
        uH = f4fma(b, p[1], uH);
        vL = f4fma(b, p[2], vL);
        vH = f4fma(b, p[3], vH);
    }
    float2 xv = __ldg((const float2*)(x) + src);   // the only random gather: 8B
    float4 mL, mH;
    mL.x = xv.x * uL.x + xv.y * vL.x; mL.y = xv.x * uL.y + xv.y * vL.y;
    mL.z = xv.x * uL.z + xv.y * vL.z; mL.w = xv.x * uL.w + xv.y * vL.w;
    mH.x = xv.x * uH.x + xv.y * vH.x; mH.y = xv.x * uH.y + xv.y * vH.y;
    mH.z = xv.x * uH.z + xv.y * vH.z; mH.w = xv.x * uH.w + xv.y * vH.w;
    float* out = d_agg1 + (size_t)dst * 8;
    red_add_v4(out, mL);
    red_add_v4(out + 4, mH);
}

// level-1 node kernel: mean + root + bias + ELU, then seg_max pooling scatter.
// Also accumulates cnt2[c1] += cnt1[n]  (replaces 1.28M edge atomics with 80K).
__global__ void k_node1(const float* __restrict__ x, const int* __restrict__ batch,
                        const int* __restrict__ cluster1,
                        const float* __restrict__ root1, const float* __restrict__ b1,
                        int N) {
    int n = blockIdx.x * blockDim.x + threadIdx.x;
    if (n >= N) return;
    int c = d_cnt1[n];
    float inv = 1.0f / (float)(c > 1 ? c : 1);
    float x0 = x[2 * n], x1 = x[2 * n + 1];
    int c1 = cluster1[n];
    int bt = batch[n];
    float* xm = d_x1max + (size_t)c1 * 8;
#pragma unroll
    for (int o = 0; o < 8; o++) {
        float h = d_agg1[(size_t)n * 8 + o] * inv + x0 * root1[o] + x1 * root1[8 + o] + b1[o];
        h = elu1(h);
        atomicMaxFloat(&xm[o], h);
    }
    atomicMax(&d_batch1[c1], bt);
    atomicAdd(&d_cnt2[c1], c);
}

// xW2 table in fp16, padded rows: [n][32 corner slots][16 half]
// Warp layout: lane = (j = o-pair 0..7, sub = node-slot 0..3); each lane holds
// 4 nodes' x1 in registers -> one LDS float2 per (k,c) feeds 4 nodes (LDS /4).
// 16 nodes per warp, 625 blocks x 128 threads covers N1=40000 exactly.
__global__ void __launch_bounds__(128) k_xw2(const float* __restrict__ W2, int N1) {
    __shared__ float sW[NUMK * 128];   // 13.8 KB: [k][c][o]
    int t = threadIdx.x;
    for (int i = t; i < NUMK * 128; i += 128) sW[i] = W2[i];
    __syncthreads();
    int w = (blockIdx.x * 128 + t) >> 5;
    int lane = t & 31;
    int j = lane & 7;            // output-channel pair (o = 2j, 2j+1)
    int sub = lane >> 3;         // node slot within quad
    int base = w * 16;
    if (base >= N1) return;
    float xv[4][8];
#pragma unroll
    for (int m = 0; m < 4; m++) {
        int node = base + m * 4 + sub;
        if (node < N1) {
            const float* xm = d_x1max + (size_t)node * 8;
#pragma unroll
            for (int c = 0; c < 8; c++) {
                float v = xm[c];
                xv[m][c] = (v == -INFINITY) ? 0.0f : v;   // seg_max empty-cluster fix
            }
        } else {
#pragma unroll
            for (int c = 0; c < 8; c++) xv[m][c] = 0.0f;
        }
    }
    for (int k = 0; k < NUMK; k++) {
        float r0[4] = {0, 0, 0, 0}, r1[4] = {0, 0, 0, 0};
#pragma unroll
        for (int c = 0; c < 8; c++) {
            float2 wc = *(const float2*)(sW + k * 128 + c * 16 + 2 * j);
#pragma unroll
            for (int m = 0; m < 4; m++) {
                r0[m] += xv[m][c] * wc.x;
                r1[m] += xv[m][c] * wc.y;
            }
        }
#pragma unroll
        for (int m = 0; m < 4; m++) {
            int node = base + m * 4 + sub;
            if (node < N1)
                *(__half2*)(d_xw2h + (size_t)node * 512 + k * 16 + 2 * j) =
                    __floats2half2_rn(r0[m], r1[m]);
        }
    }
}

// level-2 edge kernel: 2 lanes per edge, each lane owns 8 output channels.
// Each corner read = one 16B load per lane; lane pair covers one fully-used 32B sector.
__global__ void __launch_bounds__(256) k_edge2(const float* __restrict__ attr, int E) {
    int t = blockIdx.x * blockDim.x + threadIdx.x;
    int e = t >> 1;          // edge index
    int sub = t & 1;         // channel octet
    if (e >= E) return;
    int2 sd = __ldg(&d_sd2[e]);
    int s2 = sd.x;
    int d2 = sd.y;
    float a0 = attr[3 * e], a1 = attr[3 * e + 1], a2 = attr[3 * e + 2];
    float bw[8]; int kk[8];
    basis27(a0, a1, a2, bw, kk);
    const uint4* base = (const uint4*)(d_xw2h + (size_t)s2 * 512) + sub;
    uint4 q[8];
#pragma unroll
    for (int s = 0; s < 8; s++) q[s] = __ldg(base + kk[s] * 2);
    float m[8];
#pragma unroll
    for (int i = 0; i < 8; i++) m[i] = 0.0f;
#pragma unroll
    for (int s = 0; s < 8; s++) {
        float b = bw[s];
        float2 f0 = __half22float2(*(__half2*)&q[s].x);
        float2 f1 = __half22float2(*(__half2*)&q[s].y);
        float2 f2 = __half22float2(*(__half2*)&q[s].z);
        float2 f3 = __half22float2(*(__half2*)&q[s].w);
        m[0] += b * f0.x; m[1] += b * f0.y;
        m[2] += b * f1.x; m[3] += b * f1.y;
        m[4] += b * f2.x; m[5] += b * f2.y;
        m[6] += b * f3.x; m[7] += b * f3.y;
    }
    float* out = d_agg2 + (size_t)d2 * 16 + sub * 8;
    red_add_v4(out,     make_float4(m[0], m[1], m[2], m[3]));
    red_add_v4(out + 4, make_float4(m[4], m[5], m[6], m[7]));
}

// level-2 node kernel: mean + root + bias + ELU, then seg_max pooling scatter
__global__ void k_node2(const int* __restrict__ cluster2,
                        const float* __restrict__ root2, const float* __restrict__ b2,
                        int N1) {
    int n = blockIdx.x * blockDim.x + threadIdx.x;
    if (n >= N1) return;
    int c = d_cnt2[n];
    float inv = 1.0f / (float)(c > 1 ? c : 1);
    float xv[8];
#pragma unroll
    for (int i = 0; i < 8; i++) {
        float t = d_x1max[(size_t)n * 8 + i];
        xv[i] = (t == -INFINITY) ? 0.0f : t;
    }
    int c2 = cluster2[n];
    int b1v = d_batch1[n];
    int bt = b1v > 0 ? b1v : 0;
    float* xm = d_x2max + (size_t)c2 * 16;
#pragma unroll
    for (int o = 0; o < 16; o++) {
        float r = 0.0f;
#pragma unroll
        for (int i = 0; i < 8; i++) r += xv[i] * __ldg(&root2[i * 16 + o]);
        float h = d_agg2[(size_t)n * 16 + o] * inv + r + b2[o];
        h = elu1(h);
        atomicMaxFloat(&xm[o], h);
    }
    atomicMax(&d_batch2[c2], bt);
}

// scatter_mean over graphs
__global__ void k_final(int N2) {
    int n = blockIdx.x * blockDim.x + threadIdx.x;
    if (n >= N2) return;
    int b2v = d_batch2[n];
    int b = b2v > 0 ? b2v : 0;
    float v[16];
#pragma unroll
    for (int i = 0; i < 16; i++) {
        float t = d_x2max[(size_t)n * 16 + i];
        v[i] = (t == -INFINITY) ? 0.0f : t;
    }
    float* g = d_gsum + b * 16;
    red_add_v4(g,      make_float4(v[0], v[1], v[2], v[3]));
    red_add_v4(g + 4,  make_float4(v[4], v[5], v[6], v[7]));
    red_add_v4(g + 8,  make_float4(v[8], v[9], v[10], v[11]));
    red_add_v4(g + 12, make_float4(v[12], v[13], v[14], v[15]));
    atomicAdd(&d_gcnt[b], 1);
}

// B=16 MLP head, single block
__global__ void k_mlp(const float* __restrict__ fc1w, const float* __restrict__ fc1b,
                      const float* __restrict__ fc2w, const float* __restrict__ fc2b,
                      float* __restrict__ out) {
    __shared__ float g[BGRAPH * 16];
    __shared__ float hid[BGRAPH * 64];
    int t = threadIdx.x;  // 256 threads
    if (t < BGRAPH * 16) {
        int b = t >> 4;
        int c = d_gcnt[b];
        g[t] = d_gsum[t] / (float)(c > 1 ? c : 1);
    }
    __syncthreads();
    for (int i = t; i < BGRAPH * 64; i += 256) {
        int b = i >> 6, j = i & 63;
        float s = fc1b[j];
#pragma unroll
        for (int k = 0; k < 16; k++) s += g[b * 16 + k] * fc1w[k * 64 + j];
        hid[i] = elu1(s);
    }
    __syncthreads();
    if (t < BGRAPH) {
        float s = fc2b[0];
#pragma unroll
        for (int j = 0; j < 64; j++) s += hid[t * 64 + j] * fc2w[j];
        out[t] = elu1(s);
    }
}

// ---------------- launch ----------------
extern "C" void kernel_launch(void* const* d_in, const int* in_sizes, int n_in,
                              void* d_out, int out_size) {
    const float* x        = (const float*)d_in[0];
    const int*   ei       = (const int*)d_in[1];
    const float* attr     = (const float*)d_in[2];
    const int*   batch    = (const int*)d_in[3];
    const int*   cluster1 = (const int*)d_in[4];
    const int*   cluster2 = (const int*)d_in[5];
    const float* W1       = (const float*)d_in[6];
    const float* root1    = (const float*)d_in[7];
    const float* b1       = (const float*)d_in[8];
    const float* W2       = (const float*)d_in[9];
    const float* root2    = (const float*)d_in[10];
    const float* b2       = (const float*)d_in[11];
    const float* fc1w     = (const float*)d_in[12];
    const float* fc1b     = (const float*)d_in[13];
    const float* fc2w     = (const float*)d_in[14];
    const float* fc2b     = (const float*)d_in[15];
    float* out = (float*)d_out;

    int N  = in_sizes[0] / 2;
    int E  = in_sizes[1] / 2;
    int N1 = in_sizes[5];      // cluster2 has length N1
    int N2 = N1 / 2;

    const int T = 256;
    k_init<<<512, T>>>(N, N1, N2);
    k_edge1<<<(E + T - 1) / T, T>>>(ei, attr, x, W1, cluster1, E);
    k_node1<<<(N + T - 1) / T, T>>>(x, batch, cluster1, root1, b1, N);
    {
        int blocks = (N1 + 63) / 64;   // 16 nodes per warp, 4 warps per block
        k_xw2<<<blocks, 128>>>(W2, N1);
    }
    k_edge2<<<(2 * E + T - 1) / T, T>>>(attr, E);
    k_node2<<<(N1 + T - 1) / T, T>>>(cluster2, root2, b2, N1);
    k_final<<<(N2 + T - 1) / T, T>>>(N2);
    k_mlp<<<1, T>>>(fc1w, fc1b, fc2w, fc2b, out);
}

// round 11
// speedup vs baseline: 1.1048x; 1.0095x over previous
#include <cuda_runtime.h>
#include <cuda_fp16.h>
#include <math.h>

// Problem dims (fixed by the dataset)
#define NMAX   80000
#define N1MAX  40000
#define N2MAX  20000
#define EMAX   1280000
#define NUMK   27
#define BGRAPH 16

// ---------------- scratch (static __device__ — no allocations) ----------------
__device__ __align__(16) __half d_xw2h[(size_t)N1MAX * 512];   // 41 MB fp16 xW2 table
__device__ float4 d_pk[NMAX];            // packed (x0, x1, cluster1_bits, 0)
__device__ float d_agg1[NMAX * 8];
__device__ int   d_cnt1[NMAX];
__device__ float d_x1max[N1MAX * 8];
__device__ int   d_batch1[N1MAX];
__device__ float d_agg2[N1MAX * 16];
__device__ int   d_cnt2[N1MAX];
__device__ float d_x2max[N2MAX * 16];
__device__ int   d_batch2[N2MAX];
__device__ float d_gsum[BGRAPH * 16];
__device__ int   d_gcnt[BGRAPH];
__device__ int2  d_sd2[EMAX];    // packed (src2, dst2)

// ---------------- packed f32x2 helpers (sm_103a) ----------------
#define PACK2(d, lo, hi) \
    asm("mov.b64 %0, {%1, %2};" : "=l"(d) : "f"(lo), "f"(hi))
#define FMA2(acc, a, b) \
    asm("fma.rn.f32x2 %0, %1, %2, %3;" : "=l"(acc) : "l"(a), "l"(b), "l"(acc))
#define FMA2D(d, a, b, c) \
    asm("fma.rn.f32x2 %0, %1, %2, %3;" : "=l"(d) : "l"(a), "l"(b), "l"(c))
#define MUL2(d, a, b) \
    asm("mul.rn.f32x2 %0, %1, %2;" : "=l"(d) : "l"(a), "l"(b))

// ---------------- helpers ----------------
__device__ __forceinline__ float elu1(float v) {
    return v > 0.0f ? v : (expf(v) - 1.0f);
}

__device__ __forceinline__ void atomicMaxFloat(float* addr, float value) {
    if (value >= 0.0f)
        atomicMax((int*)addr, __float_as_int(value));
    else
        atomicMin((unsigned int*)addr, __float_as_uint(value));
}

__device__ __forceinline__ void red_add_v4(float* p, float4 v) {
    asm volatile("red.global.add.v4.f32 [%0], {%1,%2,%3,%4};"
                 :: "l"(p), "f"(v.x), "f"(v.y), "f"(v.z), "f"(v.w) : "memory");
}

// degree-1 open B-spline basis on 3-dim pseudo coords, K=3
__device__ __forceinline__ void basis27(float a0, float a1, float a2,
                                        float* bw, int* kk) {
    float v0 = a0 * 2.0f, v1 = a1 * 2.0f, v2 = a2 * 2.0f;
    int i0 = (int)v0; i0 = i0 < 0 ? 0 : (i0 > 1 ? 1 : i0);
    int i1 = (int)v1; i1 = i1 < 0 ? 0 : (i1 > 1 ? 1 : i1);
    int i2 = (int)v2; i2 = i2 < 0 ? 0 : (i2 > 1 ? 1 : i2);
    float f0 = v0 - (float)i0, f1 = v1 - (float)i1, f2 = v2 - (float)i2;
    float g0 = 1.0f - f0, g1 = 1.0f - f1, g2 = 1.0f - f2;
#pragma unroll
    for (int s = 0; s < 8; s++) {
        int b0 = s & 1, b1 = (s >> 1) & 1, b2 = (s >> 2) & 1;
        float w0 = b0 ? f0 : g0;
        float w1 = b1 ? f1 : g1;
        float w2 = b2 ? f2 : g2;
        bw[s] = w0 * w1 * w2;
        kk[s] = (i0 + b0) + 3 * (i1 + b1) + 9 * (i2 + b2);
    }
}

// ---------------- kernels ----------------

__global__ void k_init(const float* __restrict__ x, const int* __restrict__ cluster1,
                       int N, int N1, int N2) {
    int tid = blockIdx.x * blockDim.x + threadIdx.x;
    int stride = gridDim.x * blockDim.x;
    float4 zf4 = make_float4(0, 0, 0, 0);
    float4 nf4 = make_float4(-INFINITY, -INFINITY, -INFINITY, -INFINITY);
    for (int i = tid; i < N; i += stride) {
        float2 xv = ((const float2*)x)[i];
        d_pk[i] = make_float4(xv.x, xv.y, __int_as_float(cluster1[i]), 0.0f);
    }
    for (int i = tid; i < N * 2; i += stride)  ((float4*)d_agg1)[i] = zf4;
    for (int i = tid; i < N / 4; i += stride)  ((int4*)d_cnt1)[i] = make_int4(0, 0, 0, 0);
    for (int i = tid; i < N1 * 2; i += stride) ((float4*)d_x1max)[i] = nf4;
    for (int i = tid; i < N1; i += stride)     d_batch1[i] = -0x7fffffff - 1;
    for (int i = tid; i < N1 * 4; i += stride) ((float4*)d_agg2)[i] = zf4;
    for (int i = tid; i < N1 / 4; i += stride) ((int4*)d_cnt2)[i] = make_int4(0, 0, 0, 0);
    for (int i = tid; i < N2 * 4; i += stride) ((float4*)d_x2max)[i] = nf4;
    for (int i = tid; i < N2; i += stride)     d_batch2[i] = -0x7fffffff - 1;
    for (int i = tid; i < BGRAPH * 16; i += stride) d_gsum[i] = 0.0f;
    for (int i = tid; i < BGRAPH; i += stride) d_gcnt[i] = 0;
}

// level-1 edge kernel + bookkeeping fused. Packed f32x2 accumulation.
__global__ void __launch_bounds__(256) k_edge1(
        const int* __restrict__ ei, const float* __restrict__ attr,
        const float* __restrict__ W1, const int* __restrict__ cluster1, int E) {
    __shared__ float4 sW[NUMK * 5];  // stride 5 float4 per k: [uLo, uHi, vLo, vHi, pad]
    int t = threadIdx.x;
    if (t < NUMK * 4) {
        int k = t >> 2, j = t & 3;
        sW[k * 5 + j] = ((const float4*)W1)[t];
    }
    __syncthreads();
    int e = blockIdx.x * blockDim.x + t;
    if (e >= E) return;
    int src = ei[e];
    int dst = ei[E + e];
    float4 ps = __ldg(&d_pk[src]);         // random gather #1 (x + cluster1[src])
    int d2 = __ldg(&cluster1[dst]);        // random gather #2
    int s2 = __float_as_int(ps.z);
    d_sd2[e] = make_int2(s2, d2);
    atomicAdd(&d_cnt1[dst], 1);
    float a0 = attr[3 * e], a1 = attr[3 * e + 1], a2 = attr[3 * e + 2];
    float bw[8]; int kk[8];
    basis27(a0, a1, a2, bw, kk);
    // acc[0..3] = u rows (ch0-7), acc[4..7] = v rows (ch0-7), packed f32x2
    unsigned long long acc[8];
#pragma unroll
    for (int i = 0; i < 8; i++) acc[i] = 0ull;
#pragma unroll
    for (int s = 0; s < 8; s++) {
        unsigned long long bb; PACK2(bb, bw[s], bw[s]);
        const ulonglong2* p = reinterpret_cast<const ulonglong2*>(&sW[kk[s] * 5]);
        ulonglong2 r0 = p[0], r1 = p[1], r2 = p[2], r3 = p[3];
        FMA2(acc[0], r0.x, bb); FMA2(acc[1], r0.y, bb);
        FMA2(acc[2], r1.x, bb); FMA2(acc[3], r1.y, bb);
        FMA2(acc[4], r2.x, bb); FMA2(acc[5], r2.y, bb);
        FMA2(acc[6], r3.x, bb); FMA2(acc[7], r3.y, bb);
    }
    unsigned long long xx0, xx1;
    PACK2(xx0, ps.x, ps.x);
    PACK2(xx1, ps.y, ps.y);
    union { unsigned long long u[4]; float4 f[2]; } m;
#pragma unroll
    for (int i = 0; i < 4; i++) {
        unsigned long long tv;
        MUL2(tv, acc[4 + i], xx1);
        FMA2D(m.u[i], acc[i], xx0, tv);
    }
    float* out = d_agg1 + (size_t)dst * 8;
    red_add_v4(out, m.f[0]);
    red_add_v4(out + 4, m.f[1]);
}

// level-1 node kernel: mean + root + bias + ELU, then seg_max pooling scatter.
// Also accumulates cnt2[c1] += cnt1[n].
__global__ void k_node1(const float* __restrict__ x, const int* __restrict__ batch,
                        const int* __restrict__ cluster1,
                        const float* __restrict__ root1, const float* __restrict__ b1,
                        int N) {
    int n = blockIdx.x * blockDim.x + threadIdx.x;
    if (n >= N) return;
    int c = d_cnt1[n];
    float inv = 1.0f / (float)(c > 1 ? c : 1);
    float x0 = x[2 * n], x1 = x[2 * n + 1];
    int c1 = cluster1[n];
    int bt = batch[n];
    float* xm = d_x1max + (size_t)c1 * 8;
#pragma unroll
    for (int o = 0; o < 8; o++) {
        float h = d_agg1[(size_t)n * 8 + o] * inv + x0 * root1[o] + x1 * root1[8 + o] + b1[o];
        h = elu1(h);
        atomicMaxFloat(&xm[o], h);
    }
    atomicMax(&d_batch1[c1], bt);
    atomicAdd(&d_cnt2[c1], c);
}

// xW2 table in fp16, padded rows: [n][32 corner slots][16 half]
// Warp: lane = (j = o-pair 0..7, sub = node-slot 0..3); each lane holds 4 nodes.
__global__ void __launch_bounds__(128) k_xw2(const float* __restrict__ W2, int N1) {
    __shared__ float sW[NUMK * 128];   // 13.8 KB: [k][c][o]
    int t = threadIdx.x;
    for (int i = t; i < NUMK * 128; i += 128) sW[i] = W2[i];
    __syncthreads();
    int w = (blockIdx.x * 128 + t) >> 5;
    int lane = t & 31;
    int j = lane & 7;            // output-channel pair (o = 2j, 2j+1)
    int sub = lane >> 3;         // node slot within quad
    int base = w * 16;
    if (base >= N1) return;
    float xv[4][8];
#pragma unroll
    for (int m = 0; m < 4; m++) {
        int node = base + m * 4 + sub;
        if (node < N1) {
            const float* xm = d_x1max + (size_t)node * 8;
#pragma unroll
            for (int c = 0; c < 8; c++) {
                float v = xm[c];
                xv[m][c] = (v == -INFINITY) ? 0.0f : v;
            }
        } else {
#pragma unroll
            for (int c = 0; c < 8; c++) xv[m][c] = 0.0f;
        }
    }
    for (int k = 0; k < NUMK; k++) {
        float r0[4] = {0, 0, 0, 0}, r1[4] = {0, 0, 0, 0};
#pragma unroll
        for (int c = 0; c < 8; c++) {
            float2 wc = *(const float2*)(sW + k * 128 + c * 16 + 2 * j);
#pragma unroll
            for (int m = 0; m < 4; m++) {
                r0[m] += xv[m][c] * wc.x;
                r1[m] += xv[m][c] * wc.y;
            }
        }
#pragma unroll
        for (int m = 0; m < 4; m++) {
            int node = base + m * 4 + sub;
            if (node < N1)
                *(__half2*)(d_xw2h + (size_t)node * 512 + k * 16 + 2 * j) =
                    __floats2half2_rn(r0[m], r1[m]);
        }
    }
}

// level-2 edge kernel: 2 lanes per edge, each lane owns 8 output channels.
__global__ void __launch_bounds__(256) k_edge2(const float* __restrict__ attr, int E) {
    int t = blockIdx.x * blockDim.x + threadIdx.x;
    int e = t >> 1;          // edge index
    int sub = t & 1;         // channel octet
    if (e >= E) return;
    int2 sd = __ldg(&d_sd2[e]);
    int s2 = sd.x;
    int d2 = sd.y;
    float a0 = attr[3 * e], a1 = attr[3 * e + 1], a2 = attr[3 * e + 2];
    float bw[8]; int kk[8];
    basis27(a0, a1, a2, bw, kk);
    const uint4* base = (const uint4*)(d_xw2h + (size_t)s2 * 512) + sub;
    uint4 q[8];
#pragma unroll
    for (int s = 0; s < 8; s++) q[s] = __ldg(base + kk[s] * 2);
    unsigned long long macc[4];
#pragma unroll
    for (int i = 0; i < 4; i++) macc[i] = 0ull;
#pragma unroll
    for (int s = 0; s < 8; s++) {
        unsigned long long bb; PACK2(bb, bw[s], bw[s]);
        float2 f0 = __half22float2(*(__half2*)&q[s].x);
        float2 f1 = __half22float2(*(__half2*)&q[s].y);
        float2 f2 = __half22float2(*(__half2*)&q[s].z);
        float2 f3 = __half22float2(*(__half2*)&q[s].w);
        unsigned long long p0, p1, p2, p3;
        PACK2(p0, f0.x, f0.y); PACK2(p1, f1.x, f1.y);
        PACK2(p2, f2.x, f2.y); PACK2(p3, f3.x, f3.y);
        FMA2(macc[0], p0, bb); FMA2(macc[1], p1, bb);
        FMA2(macc[2], p2, bb); FMA2(macc[3], p3, bb);
    }
    union { unsigned long long u[4]; float4 f[2]; } m;
#pragma unroll
    for (int i = 0; i < 4; i++) m.u[i] = macc[i];
    float* out = d_agg2 + (size_t)d2 * 16 + sub * 8;
    red_add_v4(out,     m.f[0]);
    red_add_v4(out + 4, m.f[1]);
}

// level-2 node kernel: mean + root + bias + ELU, then seg_max pooling scatter
__global__ void __launch_bounds__(256) k_node2(const int* __restrict__ cluster2,
                        const float* __restrict__ root2, const float* __restrict__ b2,
                        int N1) {
    __shared__ float sroot[128];
    __shared__ float sb2[16];
    int t = threadIdx.x;
    if (t < 128) sroot[t] = root2[t];
    if (t < 16) sb2[t] = b2[t];
    __syncthreads();
    int n = blockIdx.x * blockDim.x + t;
    if (n >= N1) return;
    int c = d_cnt2[n];
    float inv = 1.0f / (float)(c > 1 ? c : 1);
    float xv[8];
#pragma unroll
    for (int i = 0; i < 8; i++) {
        float v = d_x1max[(size_t)n * 8 + i];
        xv[i] = (v == -INFINITY) ? 0.0f : v;
    }
    int c2 = cluster2[n];
    int b1v = d_batch1[n];
    int bt = b1v > 0 ? b1v : 0;
    float* xm = d_x2max + (size_t)c2 * 16;
#pragma unroll
    for (int o = 0; o < 16; o++) {
        float r = 0.0f;
#pragma unroll
        for (int i = 0; i < 8; i++) r += xv[i] * sroot[i * 16 + o];
        float h = d_agg2[(size_t)n * 16 + o] * inv + r + sb2[o];
        h = elu1(h);
        atomicMaxFloat(&xm[o], h);
    }
    atomicMax(&d_batch2[c2], bt);
}

// scatter_mean over graphs
__global__ void k_final(int N2) {
    int n = blockIdx.x * blockDim.x + threadIdx.x;
    if (n >= N2) return;
    int b2v = d_batch2[n];
    int b = b2v > 0 ? b2v : 0;
    float v[16];
#pragma unroll
    for (int i = 0; i < 16; i++) {
        float t = d_x2max[(size_t)n * 16 + i];
        v[i] = (t == -INFINITY) ? 0.0f : t;
    }
    float* g = d_gsum + b * 16;
    red_add_v4(g,      make_float4(v[0], v[1], v[2], v[3]));
    red_add_v4(g + 4,  make_float4(v[4], v[5], v[6], v[7]));
    red_add_v4(g + 8,  make_float4(v[8], v[9], v[10], v[11]));
    red_add_v4(g + 12, make_float4(v[12], v[13], v[14], v[15]));
    atomicAdd(&d_gcnt[b], 1);
}

// B=16 MLP head, single block
__global__ void k_mlp(const float* __restrict__ fc1w, const float* __restrict__ fc1b,
                      const float* __restrict__ fc2w, const float* __restrict__ fc2b,
                      float* __restrict__ out) {
    __shared__ float g[BGRAPH * 16];
    __shared__ float hid[BGRAPH * 64];
    int t = threadIdx.x;  // 256 threads
    if (t < BGRAPH * 16) {
        int b = t >> 4;
        int c = d_gcnt[b];
        g[t] = d_gsum[t] / (float)(c > 1 ? c : 1);
    }
    __syncthreads();
    for (int i = t; i < BGRAPH * 64; i += 256) {
        int b = i >> 6, j = i & 63;
        float s = fc1b[j];
#pragma unroll
        for (int k = 0; k < 16; k++) s += g[b * 16 + k] * fc1w[k * 64 + j];
        hid[i] = elu1(s);
    }
    __syncthreads();
    if (t < BGRAPH) {
        float s = fc2b[0];
#pragma unroll
        for (int j = 0; j < 64; j++) s += hid[t * 64 + j] * fc2w[j];
        out[t] = elu1(s);
    }
}

// ---------------- launch ----------------
extern "C" void kernel_launch(void* const* d_in, const int* in_sizes, int n_in,
                              void* d_out, int out_size) {
    const float* x        = (const float*)d_in[0];
    const int*   ei       = (const int*)d_in[1];
    const float* attr     = (const float*)d_in[2];
    const int*   batch    = (const int*)d_in[3];
    const int*   cluster1 = (const int*)d_in[4];
    const int*   cluster2 = (const int*)d_in[5];
    const float* W1       = (const float*)d_in[6];
    const float* root1    = (const float*)d_in[7];
    const float* b1       = (const float*)d_in[8];
    const float* W2       = (const float*)d_in[9];
    const float* root2    = (const float*)d_in[10];
    const float* b2       = (const float*)d_in[11];
    const float* fc1w     = (const float*)d_in[12];
    const float* fc1b     = (const float*)d_in[13];
    const float* fc2w     = (const float*)d_in[14];
    const float* fc2b     = (const float*)d_in[15];
    float* out = (float*)d_out;

    int N  = in_sizes[0] / 2;
    int E  = in_sizes[1] / 2;
    int N1 = in_sizes[5];      // cluster2 has length N1
    int N2 = N1 / 2;

    const int T = 256;
    k_init<<<512, T>>>(x, cluster1, N, N1, N2);
    k_edge1<<<(E + T - 1) / T, T>>>(ei, attr, W1, cluster1, E);
    k_node1<<<(N + T - 1) / T, T>>>(x, batch, cluster1, root1, b1, N);
    {
        int blocks = (N1 + 63) / 64;   // 16 nodes per warp, 4 warps per block
        k_xw2<<<blocks, 128>>>(W2, N1);
    }
    k_edge2<<<(2 * E + T - 1) / T, T>>>(attr, E);
    k_node2<<<(N1 + T - 1) / T, T>>>(cluster2, root2, b2, N1);
    k_final<<<(N2 + T - 1) / T, T>>>(N2);
    k_mlp<<<1, T>>>(fc1w, fc1b, fc2w, fc2b, out);
}

// round 12
// speedup vs baseline: 1.1341x; 1.0265x over previous
#include <cuda_runtime.h>
#include <cuda_fp16.h>
#include <math.h>

// Problem dims (fixed by the dataset)
#define NMAX   80000
#define N1MAX  40000
#define N2MAX  20000
#define EMAX   1280000
#define NUMK   27
#define BGRAPH 16

// ---------------- scratch (static __device__ — no allocations) ----------------
__device__ __align__(16) __half d_xw2h[(size_t)N1MAX * 512];   // 41 MB fp16 xW2 table
__device__ float4 d_pk[NMAX];            // packed (x0, x1, cluster1_bits, 0)
__device__ float d_agg1[NMAX * 8];
__device__ int   d_cnt1[NMAX];
__device__ float d_x1max[N1MAX * 8];
__device__ int   d_batch1[N1MAX];
__device__ float d_agg2[N1MAX * 16];
__device__ int   d_cnt2[N1MAX];
__device__ float d_x2max[N2MAX * 16];
__device__ int   d_batch2[N2MAX];
__device__ float d_gsum[BGRAPH * 16];
__device__ int   d_gcnt[BGRAPH];
__device__ int2  d_sd2[EMAX];    // packed (src2, dst2)

// ---------------- packed f32x2 helpers (sm_103a) ----------------
#define PACK2(d, lo, hi) \
    asm("mov.b64 %0, {%1, %2};" : "=l"(d) : "f"(lo), "f"(hi))
#define FMA2(acc, a, b) \
    asm("fma.rn.f32x2 %0, %1, %2, %3;" : "=l"(acc) : "l"(a), "l"(b), "l"(acc))
#define FMA2D(d, a, b, c) \
    asm("fma.rn.f32x2 %0, %1, %2, %3;" : "=l"(d) : "l"(a), "l"(b), "l"(c))
#define MUL2(d, a, b) \
    asm("mul.rn.f32x2 %0, %1, %2;" : "=l"(d) : "l"(a), "l"(b))

// ---------------- helpers ----------------
__device__ __forceinline__ float elu1(float v) {
    return v > 0.0f ? v : (expf(v) - 1.0f);
}

__device__ __forceinline__ void atomicMaxFloat(float* addr, float value) {
    if (value >= 0.0f)
        atomicMax((int*)addr, __float_as_int(value));
    else
        atomicMin((unsigned int*)addr, __float_as_uint(value));
}

__device__ __forceinline__ void red_add_v4(float* p, float4 v) {
    asm volatile("red.global.add.v4.f32 [%0], {%1,%2,%3,%4};"
                 :: "l"(p), "f"(v.x), "f"(v.y), "f"(v.z), "f"(v.w) : "memory");
}

// degree-1 open B-spline basis on 3-dim pseudo coords, K=3
__device__ __forceinline__ void basis27(float a0, float a1, float a2,
                                        float* bw, int* kk) {
    float v0 = a0 * 2.0f, v1 = a1 * 2.0f, v2 = a2 * 2.0f;
    int i0 = (int)v0; i0 = i0 < 0 ? 0 : (i0 > 1 ? 1 : i0);
    int i1 = (int)v1; i1 = i1 < 0 ? 0 : (i1 > 1 ? 1 : i1);
    int i2 = (int)v2; i2 = i2 < 0 ? 0 : (i2 > 1 ? 1 : i2);
    float f0 = v0 - (float)i0, f1 = v1 - (float)i1, f2 = v2 - (float)i2;
    float g0 = 1.0f - f0, g1 = 1.0f - f1, g2 = 1.0f - f2;
#pragma unroll
    for (int s = 0; s < 8; s++) {
        int b0 = s & 1, b1 = (s >> 1) & 1, b2 = (s >> 2) & 1;
        float w0 = b0 ? f0 : g0;
        float w1 = b1 ? f1 : g1;
        float w2 = b2 ? f2 : g2;
        bw[s] = w0 * w1 * w2;
        kk[s] = (i0 + b0) + 3 * (i1 + b1) + 9 * (i2 + b2);
    }
}

// ---------------- kernels ----------------

__global__ void k_init_a(const float* __restrict__ x, const int* __restrict__ cluster1, int N) {
    int tid = blockIdx.x * blockDim.x + threadIdx.x;
    int stride = gridDim.x * blockDim.x;
    float4 zf4 = make_float4(0, 0, 0, 0);
    for (int i = tid; i < N; i += stride) {
        float2 xv = ((const float2*)x)[i];
        d_pk[i] = make_float4(xv.x, xv.y, __int_as_float(cluster1[i]), 0.0f);
    }
    for (int i = tid; i < N * 2; i += stride)  ((float4*)d_agg1)[i] = zf4;
    for (int i = tid; i < N / 4; i += stride)  ((int4*)d_cnt1)[i] = make_int4(0, 0, 0, 0);
}

__global__ void k_init_b(int N1) {
    int tid = blockIdx.x * blockDim.x + threadIdx.x;
    int stride = gridDim.x * blockDim.x;
    float4 zf4 = make_float4(0, 0, 0, 0);
    float4 nf4 = make_float4(-INFINITY, -INFINITY, -INFINITY, -INFINITY);
    for (int i = tid; i < N1 * 2; i += stride) ((float4*)d_x1max)[i] = nf4;
    for (int i = tid; i < N1; i += stride)     d_batch1[i] = -0x7fffffff - 1;
    for (int i = tid; i < N1 * 4; i += stride) ((float4*)d_agg2)[i] = zf4;
    for (int i = tid; i < N1 / 4; i += stride) ((int4*)d_cnt2)[i] = make_int4(0, 0, 0, 0);
}

__global__ void k_init_c(int N2) {
    int tid = blockIdx.x * blockDim.x + threadIdx.x;
    int stride = gridDim.x * blockDim.x;
    float4 nf4 = make_float4(-INFINITY, -INFINITY, -INFINITY, -INFINITY);
    for (int i = tid; i < N2 * 4; i += stride) ((float4*)d_x2max)[i] = nf4;
    for (int i = tid; i < N2; i += stride)     d_batch2[i] = -0x7fffffff - 1;
    for (int i = tid; i < BGRAPH * 16; i += stride) d_gsum[i] = 0.0f;
    for (int i = tid; i < BGRAPH; i += stride) d_gcnt[i] = 0;
}

// level-1 edge kernel + bookkeeping fused. W1 in smem as fp16 (halves LDS volume
// and conflict degree). Accumulate b*u, b*v in packed f32x2; combine with x at end.
__global__ void __launch_bounds__(256) k_edge1(
        const int* __restrict__ ei, const float* __restrict__ attr,
        const float* __restrict__ W1, const int* __restrict__ cluster1, int E) {
    __shared__ uint4 sWh[NUMK * 3];  // per k: [u 8 half][v 8 half][pad] (48B stride)
    int t = threadIdx.x;
    if (t < NUMK * 2) {
        int k = t >> 1, p = t & 1;
        const float* w = W1 + (k * 2 + p) * 8;
        __half2 h0 = __floats2half2_rn(w[0], w[1]);
        __half2 h1 = __floats2half2_rn(w[2], w[3]);
        __half2 h2 = __floats2half2_rn(w[4], w[5]);
        __half2 h3 = __floats2half2_rn(w[6], w[7]);
        uint4 q;
        q.x = *(unsigned*)&h0; q.y = *(unsigned*)&h1;
        q.z = *(unsigned*)&h2; q.w = *(unsigned*)&h3;
        sWh[k * 3 + p] = q;
    }
    __syncthreads();
    int e = blockIdx.x * blockDim.x + t;
    if (e >= E) return;
    int src = ei[e];
    int dst = ei[E + e];
    float4 ps = __ldg(&d_pk[src]);         // random gather #1 (x + cluster1[src])
    int d2 = __ldg(&cluster1[dst]);        // random gather #2
    d_sd2[e] = make_int2(__float_as_int(ps.z), d2);
    atomicAdd(&d_cnt1[dst], 1);
    float a0 = attr[3 * e], a1 = attr[3 * e + 1], a2 = attr[3 * e + 2];
    float bw[8]; int kk[8];
    basis27(a0, a1, a2, bw, kk);
    unsigned long long mu[4], mv[4];
#pragma unroll
    for (int i = 0; i < 4; i++) { mu[i] = 0ull; mv[i] = 0ull; }
#pragma unroll
    for (int s = 0; s < 8; s++) {
        uint4 qu = sWh[kk[s] * 3];
        uint4 qv = sWh[kk[s] * 3 + 1];
        unsigned long long bb; PACK2(bb, bw[s], bw[s]);
        float2 u0 = __half22float2(*(__half2*)&qu.x);
        float2 u1 = __half22float2(*(__half2*)&qu.y);
        float2 u2 = __half22float2(*(__half2*)&qu.z);
        float2 u3 = __half22float2(*(__half2*)&qu.w);
        float2 v0 = __half22float2(*(__half2*)&qv.x);
        float2 v1 = __half22float2(*(__half2*)&qv.y);
        float2 v2 = __half22float2(*(__half2*)&qv.z);
        float2 v3 = __half22float2(*(__half2*)&qv.w);
        unsigned long long p0, p1, p2, p3;
        PACK2(p0, u0.x, u0.y); PACK2(p1, u1.x, u1.y);
        PACK2(p2, u2.x, u2.y); PACK2(p3, u3.x, u3.y);
        FMA2(mu[0], p0, bb); FMA2(mu[1], p1, bb);
        FMA2(mu[2], p2, bb); FMA2(mu[3], p3, bb);
        PACK2(p0, v0.x, v0.y); PACK2(p1, v1.x, v1.y);
        PACK2(p2, v2.x, v2.y); PACK2(p3, v3.x, v3.y);
        FMA2(mv[0], p0, bb); FMA2(mv[1], p1, bb);
        FMA2(mv[2], p2, bb); FMA2(mv[3], p3, bb);
    }
    unsigned long long xx0, xx1;
    PACK2(xx0, ps.x, ps.x);
    PACK2(xx1, ps.y, ps.y);
    union { unsigned long long u[4]; float4 f[2]; } m;
#pragma unroll
    for (int i = 0; i < 4; i++) {
        unsigned long long tv;
        MUL2(tv, mv[i], xx1);
        FMA2D(m.u[i], mu[i], xx0, tv);
    }
    float* out = d_agg1 + (size_t)dst * 8;
    red_add_v4(out, m.f[0]);
    red_add_v4(out + 4, m.f[1]);
}

// level-1 node kernel: mean + root + bias + ELU, then seg_max pooling scatter.
// Also accumulates cnt2[c1] += cnt1[n].
__global__ void k_node1(const float* __restrict__ x, const int* __restrict__ batch,
                        const int* __restrict__ cluster1,
                        const float* __restrict__ root1, const float* __restrict__ b1,
                        int N) {
    int n = blockIdx.x * blockDim.x + threadIdx.x;
    if (n >= N) return;
    int c = d_cnt1[n];
    float inv = 1.0f / (float)(c > 1 ? c : 1);
    float x0 = x[2 * n], x1 = x[2 * n + 1];
    int c1 = cluster1[n];
    int bt = batch[n];
    float* xm = d_x1max + (size_t)c1 * 8;
#pragma unroll
    for (int o = 0; o < 8; o++) {
        float h = d_agg1[(size_t)n * 8 + o] * inv + x0 * root1[o] + x1 * root1[8 + o] + b1[o];
        h = elu1(h);
        atomicMaxFloat(&xm[o], h);
    }
    atomicMax(&d_batch1[c1], bt);
    atomicAdd(&d_cnt2[c1], c);
}

// xW2 table in fp16, padded rows: [n][32 corner slots][16 half]
// 8 nodes per warp (lane = o-pair j 0..7 x node-slot sub 0..3, 2 nodes per lane),
// packed f32x2 FMA: 16 FMA2 per k per warp.
__global__ void __launch_bounds__(128) k_xw2(const float* __restrict__ W2, int N1) {
    __shared__ float sW[NUMK * 128];   // 13.8 KB: [k][c][o]
    int t = threadIdx.x;
    for (int i = t; i < NUMK * 128; i += 128) sW[i] = W2[i];
    __syncthreads();
    int w = (blockIdx.x * 128 + t) >> 5;
    int lane = t & 31;
    int j = lane & 7;            // output-channel pair (o = 2j, 2j+1)
    int sub = lane >> 3;         // node slot within quad
    int base = w * 8;
    if (base >= N1) return;
    unsigned long long xp[2][8];   // (xv, xv) packed per node per input channel
#pragma unroll
    for (int m = 0; m < 2; m++) {
        int node = base + m * 4 + sub;
        if (node < N1) {
            const float* xm = d_x1max + (size_t)node * 8;
#pragma unroll
            for (int c = 0; c < 8; c++) {
                float v = xm[c];
                v = (v == -INFINITY) ? 0.0f : v;   // seg_max empty-cluster fix
                PACK2(xp[m][c], v, v);
            }
        } else {
#pragma unroll
            for (int c = 0; c < 8; c++) xp[m][c] = 0ull;
        }
    }
    for (int k = 0; k < NUMK; k++) {
        unsigned long long r01[2] = {0ull, 0ull};
#pragma unroll
        for (int c = 0; c < 8; c++) {
            unsigned long long wc = *(const unsigned long long*)(sW + k * 128 + c * 16 + 2 * j);
            FMA2(r01[0], wc, xp[0][c]);
            FMA2(r01[1], wc, xp[1][c]);
        }
#pragma unroll
        for (int m = 0; m < 2; m++) {
            int node = base + m * 4 + sub;
            if (node < N1) {
                union { unsigned long long u; float2 f; } r;
                r.u = r01[m];
                *(__half2*)(d_xw2h + (size_t)node * 512 + k * 16 + 2 * j) =
                    __floats2half2_rn(r.f.x, r.f.y);
            }
        }
    }
}

// level-2 edge kernel: 2 lanes per edge, each lane owns 8 output channels.
__global__ void __launch_bounds__(256) k_edge2(const float* __restrict__ attr, int E) {
    int t = blockIdx.x * blockDim.x + threadIdx.x;
    int e = t >> 1;          // edge index
    int sub = t & 1;         // channel octet
    if (e >= E) return;
    int2 sd = __ldg(&d_sd2[e]);
    int s2 = sd.x;
    int d2 = sd.y;
    float a0 = attr[3 * e], a1 = attr[3 * e + 1], a2 = attr[3 * e + 2];
    float bw[8]; int kk[8];
    basis27(a0, a1, a2, bw, kk);
    const uint4* base = (const uint4*)(d_xw2h + (size_t)s2 * 512) + sub;
    uint4 q[8];
#pragma unroll
    for (int s = 0; s < 8; s++) q[s] = __ldg(base + kk[s] * 2);
    unsigned long long macc[4];
#pragma unroll
    for (int i = 0; i < 4; i++) macc[i] = 0ull;
#pragma unroll
    for (int s = 0; s < 8; s++) {
        unsigned long long bb; PACK2(bb, bw[s], bw[s]);
        float2 f0 = __half22float2(*(__half2*)&q[s].x);
        float2 f1 = __half22float2(*(__half2*)&q[s].y);
        float2 f2 = __half22float2(*(__half2*)&q[s].z);
        float2 f3 = __half22float2(*(__half2*)&q[s].w);
        unsigned long long p0, p1, p2, p3;
        PACK2(p0, f0.x, f0.y); PACK2(p1, f1.x, f1.y);
        PACK2(p2, f2.x, f2.y); PACK2(p3, f3.x, f3.y);
        FMA2(macc[0], p0, bb); FMA2(macc[1], p1, bb);
        FMA2(macc[2], p2, bb); FMA2(macc[3], p3, bb);
    }
    union { unsigned long long u[4]; float4 f[2]; } m;
#pragma unroll
    for (int i = 0; i < 4; i++) m.u[i] = macc[i];
    float* out = d_agg2 + (size_t)d2 * 16 + sub * 8;
    red_add_v4(out,     m.f[0]);
    red_add_v4(out + 4, m.f[1]);
}

// level-2 node kernel: mean + root + bias + ELU, then seg_max pooling scatter
__global__ void __launch_bounds__(256) k_node2(const int* __restrict__ cluster2,
                        const float* __restrict__ root2, const float* __restrict__ b2,
                        int N1) {
    __shared__ float sroot[128];
    __shared__ float sb2[16];
    int t = threadIdx.x;
    if (t < 128) sroot[t] = root2[t];
    if (t < 16) sb2[t] = b2[t];
    __syncthreads();
    int n = blockIdx.x * blockDim.x + t;
    if (n >= N1) return;
    int c = d_cnt2[n];
    float inv = 1.0f / (float)(c > 1 ? c : 1);
    float xv[8];
#pragma unroll
    for (int i = 0; i < 8; i++) {
        float v = d_x1max[(size_t)n * 8 + i];
        xv[i] = (v == -INFINITY) ? 0.0f : v;
    }
    int c2 = cluster2[n];
    int b1v = d_batch1[n];
    int bt = b1v > 0 ? b1v : 0;
    float* xm = d_x2max + (size_t)c2 * 16;
#pragma unroll
    for (int o = 0; o < 16; o++) {
        float r = 0.0f;
#pragma unroll
        for (int i = 0; i < 8; i++) r += xv[i] * sroot[i * 16 + o];
        float h = d_agg2[(size_t)n * 16 + o] * inv + r + sb2[o];
        h = elu1(h);
        atomicMaxFloat(&xm[o], h);
    }
    atomicMax(&d_batch2[c2], bt);
}

// scatter_mean over graphs
__global__ void k_final(int N2) {
    int n = blockIdx.x * blockDim.x + threadIdx.x;
    if (n >= N2) return;
    int b2v = d_batch2[n];
    int b = b2v > 0 ? b2v : 0;
    float v[16];
#pragma unroll
    for (int i = 0; i < 16; i++) {
        float t = d_x2max[(size_t)n * 16 + i];
        v[i] = (t == -INFINITY) ? 0.0f : t;
    }
    float* g = d_gsum + b * 16;
    red_add_v4(g,      make_float4(v[0], v[1], v[2], v[3]));
    red_add_v4(g + 4,  make_float4(v[4], v[5], v[6], v[7]));
    red_add_v4(g + 8,  make_float4(v[8], v[9], v[10], v[11]));
    red_add_v4(g + 12, make_float4(v[12], v[13], v[14], v[15]));
    atomicAdd(&d_gcnt[b], 1);
}

// B=16 MLP head, single block
__global__ void k_mlp(const float* __restrict__ fc1w, const float* __restrict__ fc1b,
                      const float* __restrict__ fc2w, const float* __restrict__ fc2b,
                      float* __restrict__ out) {
    __shared__ float g[BGRAPH * 16];
    __shared__ float hid[BGRAPH * 64];
    int t = threadIdx.x;  // 256 threads
    if (t < BGRAPH * 16) {
        int b = t >> 4;
        int c = d_gcnt[b];
        g[t] = d_gsum[t] / (float)(c > 1 ? c : 1);
    }
    __syncthreads();
    for (int i = t; i < BGRAPH * 64; i += 256) {
        int b = i >> 6, j = i & 63;
        float s = fc1b[j];
#pragma unroll
        for (int k = 0; k < 16; k++) s += g[b * 16 + k] * fc1w[k * 64 + j];
        hid[i] = elu1(s);
    }
    __syncthreads();
    if (t < BGRAPH) {
        float s = fc2b[0];
#pragma unroll
        for (int j = 0; j < 64; j++) s += hid[t * 64 + j] * fc2w[j];
        out[t] = elu1(s);
    }
}

// ---------------- launch ----------------
extern "C" void kernel_launch(void* const* d_in, const int* in_sizes, int n_in,
                              void* d_out, int out_size) {
    const float* x        = (const float*)d_in[0];
    const int*   ei       = (const int*)d_in[1];
    const float* attr     = (const float*)d_in[2];
    const int*   batch    = (const int*)d_in[3];
    const int*   cluster1 = (const int*)d_in[4];
    const int*   cluster2 = (const int*)d_in[5];
    const float* W1       = (const float*)d_in[6];
    const float* root1    = (const float*)d_in[7];
    const float* b1       = (const float*)d_in[8];
    const float* W2       = (const float*)d_in[9];
    const float* root2    = (const float*)d_in[10];
    const float* b2       = (const float*)d_in[11];
    const float* fc1w     = (const float*)d_in[12];
    const float* fc1b     = (const float*)d_in[13];
    const float* fc2w     = (const float*)d_in[14];
    const float* fc2b     = (const float*)d_in[15];
    float* out = (float*)d_out;

    int N  = in_sizes[0] / 2;
    int E  = in_sizes[1] / 2;
    int N1 = in_sizes[5];      // cluster2 has length N1
    int N2 = N1 / 2;

    const int T = 256;
    k_init_a<<<256, T>>>(x, cluster1, N);
    k_init_b<<<256, T>>>(N1);
    k_init_c<<<128, T>>>(N2);
    k_edge1<<<(E + T - 1) / T, T>>>(ei, attr, W1, cluster1, E);
    k_node1<<<(N + T - 1) / T, T>>>(x, batch, cluster1, root1, b1, N);
    {
        int blocks = (N1 + 31) / 32;   // 8 nodes per warp, 4 warps per block
        k_xw2<<<blocks, 128>>>(W2, N1);
    }
    k_edge2<<<(2 * E + T - 1) / T, T>>>(attr, E);
    k_node2<<<(N1 + T - 1) / T, T>>>(cluster2, root2, b2, N1);
    k_final<<<(N2 + T - 1) / T, T>>>(N2);
    k_mlp<<<1, T>>>(fc1w, fc1b, fc2w, fc2b, out);
}

// round 14
// speedup vs baseline: 1.2240x; 1.0793x over previous
#include <cuda_runtime.h>
#include <cuda_fp16.h>
#include <math.h>

// Problem dims (fixed by the dataset)
#define NMAX   80000
#define N1MAX  40000
#define N2MAX  20000
#define EMAX   1280000
#define NUMK   27
#define BGRAPH 16

// ---------------- scratch (static __device__ — no allocations) ----------------
__device__ __align__(16) __half d_xw2h[(size_t)N1MAX * 512];   // 41 MB fp16 xW2 table
__device__ float4 d_pk[NMAX];            // packed (x0, x1, cluster1_bits, 0)
__device__ __align__(16) __half d_agg1h[NMAX * 8];    // fp16 level-1 aggregation
__device__ int   d_cnt1[NMAX];
__device__ float d_x1max[N1MAX * 8];
__device__ int   d_batch1[N1MAX];
__device__ __align__(16) __half d_agg2h[N1MAX * 16];  // fp16 level-2 aggregation
__device__ int   d_cnt2[N1MAX];
__device__ float d_x2max[N2MAX * 16];
__device__ int   d_batch2[N2MAX];
__device__ float d_gsum[BGRAPH * 16];
__device__ int   d_gcnt[BGRAPH];
__device__ int2  d_sd2[EMAX];    // packed (src2, dst2)

// ---------------- packed f32x2 helpers (sm_103a) ----------------
#define PACK2(d, lo, hi) \
    asm("mov.b64 %0, {%1, %2};" : "=l"(d) : "f"(lo), "f"(hi))
#define FMA2(acc, a, b) \
    asm("fma.rn.f32x2 %0, %1, %2, %3;" : "=l"(acc) : "l"(a), "l"(b), "l"(acc))
#define FMA2D(d, a, b, c) \
    asm("fma.rn.f32x2 %0, %1, %2, %3;" : "=l"(d) : "l"(a), "l"(b), "l"(c))
#define MUL2(d, a, b) \
    asm("mul.rn.f32x2 %0, %1, %2;" : "=l"(d) : "l"(a), "l"(b))

// ---------------- helpers ----------------
__device__ __forceinline__ float elu1(float v) {
    return v > 0.0f ? v : (expf(v) - 1.0f);
}

__device__ __forceinline__ void atomicMaxFloat(float* addr, float value) {
    if (value >= 0.0f)
        atomicMax((int*)addr, __float_as_int(value));
    else
        atomicMin((unsigned int*)addr, __float_as_uint(value));
}

__device__ __forceinline__ void red_add_v4(float* p, float4 v) {
    asm volatile("red.global.add.v4.f32 [%0], {%1,%2,%3,%4};"
                 :: "l"(p), "f"(v.x), "f"(v.y), "f"(v.z), "f"(v.w) : "memory");
}

// 8 halves (4 x f16x2) in ONE vector reduction
__device__ __forceinline__ void red_add_v4h2(__half* p, unsigned h0, unsigned h1,
                                             unsigned h2, unsigned h3) {
    asm volatile("red.global.add.noftz.v4.f16x2 [%0], {%1,%2,%3,%4};"
                 :: "l"(p), "r"(h0), "r"(h1), "r"(h2), "r"(h3) : "memory");
}

__device__ __forceinline__ unsigned f32x2_to_h2(unsigned long long v) {
    union { unsigned long long u; float2 f; } r;
    r.u = v;
    __half2 h = __floats2half2_rn(r.f.x, r.f.y);
    return *(unsigned*)&h;
}

// degree-1 open B-spline basis on 3-dim pseudo coords, K=3
__device__ __forceinline__ void basis27(float a0, float a1, float a2,
                                        float* bw, int* kk) {
    float v0 = a0 * 2.0f, v1 = a1 * 2.0f, v2 = a2 * 2.0f;
    int i0 = (int)v0; i0 = i0 < 0 ? 0 : (i0 > 1 ? 1 : i0);
    int i1 = (int)v1; i1 = i1 < 0 ? 0 : (i1 > 1 ? 1 : i1);
    int i2 = (int)v2; i2 = i2 < 0 ? 0 : (i2 > 1 ? 1 : i2);
    float f0 = v0 - (float)i0, f1 = v1 - (float)i1, f2 = v2 - (float)i2;
    float g0 = 1.0f - f0, g1 = 1.0f - f1, g2 = 1.0f - f2;
#pragma unroll
    for (int s = 0; s < 8; s++) {
        int b0 = s & 1, b1 = (s >> 1) & 1, b2 = (s >> 2) & 1;
        float w0 = b0 ? f0 : g0;
        float w1 = b1 ? f1 : g1;
        float w2 = b2 ? f2 : g2;
        bw[s] = w0 * w1 * w2;
        kk[s] = (i0 + b0) + 3 * (i1 + b1) + 9 * (i2 + b2);
    }
}

// ---------------- kernels ----------------

__global__ void k_init_a(const float* __restrict__ x, const int* __restrict__ cluster1, int N) {
    int tid = blockIdx.x * blockDim.x + threadIdx.x;
    int stride = gridDim.x * blockDim.x;
    uint4 z4 = make_uint4(0, 0, 0, 0);
    for (int i = tid; i < N; i += stride) {
        float2 xv = ((const float2*)x)[i];
        d_pk[i] = make_float4(xv.x, xv.y, __int_as_float(cluster1[i]), 0.0f);
    }
    for (int i = tid; i < N; i += stride)      ((uint4*)d_agg1h)[i] = z4;   // 8 halves/node
    for (int i = tid; i < N / 4; i += stride)  ((int4*)d_cnt1)[i] = make_int4(0, 0, 0, 0);
}

__global__ void k_init_b(int N1) {
    int tid = blockIdx.x * blockDim.x + threadIdx.x;
    int stride = gridDim.x * blockDim.x;
    uint4 z4 = make_uint4(0, 0, 0, 0);
    float4 nf4 = make_float4(-INFINITY, -INFINITY, -INFINITY, -INFINITY);
    for (int i = tid; i < N1 * 2; i += stride) ((float4*)d_x1max)[i] = nf4;
    for (int i = tid; i < N1; i += stride)     d_batch1[i] = -0x7fffffff - 1;
    for (int i = tid; i < N1 * 2; i += stride) ((uint4*)d_agg2h)[i] = z4;   // 16 halves/node
    for (int i = tid; i < N1 / 4; i += stride) ((int4*)d_cnt2)[i] = make_int4(0, 0, 0, 0);
}

__global__ void k_init_c(int N2) {
    int tid = blockIdx.x * blockDim.x + threadIdx.x;
    int stride = gridDim.x * blockDim.x;
    float4 nf4 = make_float4(-INFINITY, -INFINITY, -INFINITY, -INFINITY);
    for (int i = tid; i < N2 * 4; i += stride) ((float4*)d_x2max)[i] = nf4;
    for (int i = tid; i < N2; i += stride)     d_batch2[i] = -0x7fffffff - 1;
    for (int i = tid; i < BGRAPH * 16; i += stride) d_gsum[i] = 0.0f;
    for (int i = tid; i < BGRAPH; i += stride) d_gcnt[i] = 0;
}

// level-1 edge kernel + bookkeeping fused. W1 in smem as fp16.
// Message reduced with ONE red.v4.f16x2 (8 halves).
__global__ void __launch_bounds__(256, 4) k_edge1(
        const int* __restrict__ ei, const float* __restrict__ attr,
        const float* __restrict__ W1, const int* __restrict__ cluster1, int E) {
    __shared__ uint4 sWh[NUMK * 3];  // per k: [u 8 half][v 8 half][pad] (48B stride)
    int t = threadIdx.x;
    if (t < NUMK * 2) {
        int k = t >> 1, p = t & 1;
        const float* w = W1 + (k * 2 + p) * 8;
        __half2 h0 = __floats2half2_rn(w[0], w[1]);
        __half2 h1 = __floats2half2_rn(w[2], w[3]);
        __half2 h2 = __floats2half2_rn(w[4], w[5]);
        __half2 h3 = __floats2half2_rn(w[6], w[7]);
        uint4 q;
        q.x = *(unsigned*)&h0; q.y = *(unsigned*)&h1;
        q.z = *(unsigned*)&h2; q.w = *(unsigned*)&h3;
        sWh[k * 3 + p] = q;
    }
    __syncthreads();
    int e = blockIdx.x * blockDim.x + t;
    if (e >= E) return;
    int src = ei[e];
    int dst = ei[E + e];
    float4 ps = __ldg(&d_pk[src]);         // random gather #1 (x + cluster1[src])
    int d2 = __ldg(&cluster1[dst]);        // random gather #2
    d_sd2[e] = make_int2(__float_as_int(ps.z), d2);
    atomicAdd(&d_cnt1[dst], 1);
    float a0 = attr[3 * e], a1 = attr[3 * e + 1], a2 = attr[3 * e + 2];
    float bw[8]; int kk[8];
    basis27(a0, a1, a2, bw, kk);
    unsigned long long mu[4], mv[4];
#pragma unroll
    for (int i = 0; i < 4; i++) { mu[i] = 0ull; mv[i] = 0ull; }
#pragma unroll
    for (int s = 0; s < 8; s++) {
        uint4 qu = sWh[kk[s] * 3];
        uint4 qv = sWh[kk[s] * 3 + 1];
        unsigned long long bb; PACK2(bb, bw[s], bw[s]);
        float2 u0 = __half22float2(*(__half2*)&qu.x);
        float2 u1 = __half22float2(*(__half2*)&qu.y);
        float2 u2 = __half22float2(*(__half2*)&qu.z);
        float2 u3 = __half22float2(*(__half2*)&qu.w);
        float2 v0 = __half22float2(*(__half2*)&qv.x);
        float2 v1 = __half22float2(*(__half2*)&qv.y);
        float2 v2 = __half22float2(*(__half2*)&qv.z);
        float2 v3 = __half22float2(*(__half2*)&qv.w);
        unsigned long long p0, p1, p2, p3;
        PACK2(p0, u0.x, u0.y); PACK2(p1, u1.x, u1.y);
        PACK2(p2, u2.x, u2.y); PACK2(p3, u3.x, u3.y);
        FMA2(mu[0], p0, bb); FMA2(mu[1], p1, bb);
        FMA2(mu[2], p2, bb); FMA2(mu[3], p3, bb);
        PACK2(p0, v0.x, v0.y); PACK2(p1, v1.x, v1.y);
        PACK2(p2, v2.x, v2.y); PACK2(p3, v3.x, v3.y);
        FMA2(mv[0], p0, bb); FMA2(mv[1], p1, bb);
        FMA2(mv[2], p2, bb); FMA2(mv[3], p3, bb);
    }
    unsigned long long xx0, xx1;
    PACK2(xx0, ps.x, ps.x);
    PACK2(xx1, ps.y, ps.y);
    unsigned h[4];
#pragma unroll
    for (int i = 0; i < 4; i++) {
        unsigned long long tv, mm;
        MUL2(tv, mv[i], xx1);
        FMA2D(mm, mu[i], xx0, tv);
        h[i] = f32x2_to_h2(mm);
    }
    red_add_v4h2(d_agg1h + (size_t)dst * 8, h[0], h[1], h[2], h[3]);
}

// level-1 node kernel: mean + root + bias + ELU, then seg_max pooling scatter.
// Also accumulates cnt2[c1] += cnt1[n].
__global__ void k_node1(const float* __restrict__ x, const int* __restrict__ batch,
                        const int* __restrict__ cluster1,
                        const float* __restrict__ root1, const float* __restrict__ b1,
                        int N) {
    int n = blockIdx.x * blockDim.x + threadIdx.x;
    if (n >= N) return;
    int c = d_cnt1[n];
    float inv = 1.0f / (float)(c > 1 ? c : 1);
    float x0 = x[2 * n], x1 = x[2 * n + 1];
    int c1 = cluster1[n];
    int bt = batch[n];
    uint4 q = *(const uint4*)(d_agg1h + (size_t)n * 8);
    float a[8];
    {
        float2 f0 = __half22float2(*(__half2*)&q.x);
        float2 f1 = __half22float2(*(__half2*)&q.y);
        float2 f2 = __half22float2(*(__half2*)&q.z);
        float2 f3 = __half22float2(*(__half2*)&q.w);
        a[0] = f0.x; a[1] = f0.y; a[2] = f1.x; a[3] = f1.y;
        a[4] = f2.x; a[5] = f2.y; a[6] = f3.x; a[7] = f3.y;
    }
    float* xm = d_x1max + (size_t)c1 * 8;
#pragma unroll
    for (int o = 0; o < 8; o++) {
        float h = a[o] * inv + x0 * root1[o] + x1 * root1[8 + o] + b1[o];
        h = elu1(h);
        atomicMaxFloat(&xm[o], h);
    }
    atomicMax(&d_batch1[c1], bt);
    atomicAdd(&d_cnt2[c1], c);
}

// xW2 table in fp16, padded rows: [n][32 corner slots][16 half]
// 8 nodes per warp, packed f32x2 FMA.
__global__ void __launch_bounds__(128) k_xw2(const float* __restrict__ W2, int N1) {
    __shared__ float sW[NUMK * 128];   // 13.8 KB: [k][c][o]
    int t = threadIdx.x;
    for (int i = t; i < NUMK * 128; i += 128) sW[i] = W2[i];
    __syncthreads();
    int w = (blockIdx.x * 128 + t) >> 5;
    int lane = t & 31;
    int j = lane & 7;            // output-channel pair (o = 2j, 2j+1)
    int sub = lane >> 3;         // node slot within quad
    int base = w * 8;
    if (base >= N1) return;
    unsigned long long xp[2][8];   // (xv, xv) packed per node per input channel
#pragma unroll
    for (int m = 0; m < 2; m++) {
        int node = base + m * 4 + sub;
        if (node < N1) {
            const float* xm = d_x1max + (size_t)node * 8;
#pragma unroll
            for (int c = 0; c < 8; c++) {
                float v = xm[c];
                v = (v == -INFINITY) ? 0.0f : v;   // seg_max empty-cluster fix
                PACK2(xp[m][c], v, v);
            }
        } else {
#pragma unroll
            for (int c = 0; c < 8; c++) xp[m][c] = 0ull;
        }
    }
    for (int k = 0; k < NUMK; k++) {
        unsigned long long r01[2] = {0ull, 0ull};
#pragma unroll
        for (int c = 0; c < 8; c++) {
            unsigned long long wc = *(const unsigned long long*)(sW + k * 128 + c * 16 + 2 * j);
            FMA2(r01[0], wc, xp[0][c]);
            FMA2(r01[1], wc, xp[1][c]);
        }
#pragma unroll
        for (int m = 0; m < 2; m++) {
            int node = base + m * 4 + sub;
            if (node < N1) {
                union { unsigned long long u; float2 f; } r;
                r.u = r01[m];
                *(__half2*)(d_xw2h + (size_t)node * 512 + k * 16 + 2 * j) =
                    __floats2half2_rn(r.f.x, r.f.y);
            }
        }
    }
}

// level-2 edge kernel: 2 lanes per edge, each lane owns 8 output channels.
// Message reduced with ONE red.v4.f16x2 per lane (2 per edge, was 4 f32 REDs).
__global__ void __launch_bounds__(256, 4) k_edge2(const float* __restrict__ attr, int E) {
    int t = blockIdx.x * blockDim.x + threadIdx.x;
    int e = t >> 1;          // edge index
    int sub = t & 1;         // channel octet
    if (e >= E) return;
    int2 sd = __ldg(&d_sd2[e]);
    int s2 = sd.x;
    int d2 = sd.y;
    float a0 = attr[3 * e], a1 = attr[3 * e + 1], a2 = attr[3 * e + 2];
    float bw[8]; int kk[8];
    basis27(a0, a1, a2, bw, kk);
    const uint4* base = (const uint4*)(d_xw2h + (size_t)s2 * 512) + sub;
    uint4 q[8];
#pragma unroll
    for (int s = 0; s < 8; s++) q[s] = __ldg(base + kk[s] * 2);
    unsigned long long macc[4];
#pragma unroll
    for (int i = 0; i < 4; i++) macc[i] = 0ull;
#pragma unroll
    for (int s = 0; s < 8; s++) {
        unsigned long long bb; PACK2(bb, bw[s], bw[s]);
        float2 f0 = __half22float2(*(__half2*)&q[s].x);
        float2 f1 = __half22float2(*(__half2*)&q[s].y);
        float2 f2 = __half22float2(*(__half2*)&q[s].z);
        float2 f3 = __half22float2(*(__half2*)&q[s].w);
        unsigned long long p0, p1, p2, p3;
        PACK2(p0, f0.x, f0.y); PACK2(p1, f1.x, f1.y);
        PACK2(p2, f2.x, f2.y); PACK2(p3, f3.x, f3.y);
        FMA2(macc[0], p0, bb); FMA2(macc[1], p1, bb);
        FMA2(macc[2], p2, bb); FMA2(macc[3], p3, bb);
    }
    unsigned h0 = f32x2_to_h2(macc[0]);
    unsigned h1 = f32x2_to_h2(macc[1]);
    unsigned h2 = f32x2_to_h2(macc[2]);
    unsigned h3 = f32x2_to_h2(macc[3]);
    red_add_v4h2(d_agg2h + (size_t)d2 * 16 + sub * 8, h0, h1, h2, h3);
}

// level-2 node kernel: mean + root + bias + ELU, then seg_max pooling scatter
__global__ void __launch_bounds__(256) k_node2(const int* __restrict__ cluster2,
                        const float* __restrict__ root2, const float* __restrict__ b2,
                        int N1) {
    __shared__ float sroot[128];
    __shared__ float sb2[16];
    int t = threadIdx.x;
    if (t < 128) sroot[t] = root2[t];
    if (t < 16) sb2[t] = b2[t];
    __syncthreads();
    int n = blockIdx.x * blockDim.x + t;
    if (n >= N1) return;
    int c = d_cnt2[n];
    float inv = 1.0f / (float)(c > 1 ? c : 1);
    float xv[8];
#pragma unroll
    for (int i = 0; i < 8; i++) {
        float v = d_x1max[(size_t)n * 8 + i];
        xv[i] = (v == -INFINITY) ? 0.0f : v;
    }
    float a[16];
    {
        uint4 qa = *(const uint4*)(d_agg2h + (size_t)n * 16);
        uint4 qb = *(const uint4*)(d_agg2h + (size_t)n * 16 + 8);
        float2 f;
        f = __half22float2(*(__half2*)&qa.x); a[0] = f.x; a[1] = f.y;
        f = __half22float2(*(__half2*)&qa.y); a[2] = f.x; a[3] = f.y;
        f = __half22float2(*(__half2*)&qa.z); a[4] = f.x; a[5] = f.y;
        f = __half22float2(*(__half2*)&qa.w); a[6] = f.x; a[7] = f.y;
        f = __half22float2(*(__half2*)&qb.x); a[8] = f.x; a[9] = f.y;
        f = __half22float2(*(__half2*)&qb.y); a[10] = f.x; a[11] = f.y;
        f = __half22float2(*(__half2*)&qb.z); a[12] = f.x; a[13] = f.y;
        f = __half22float2(*(__half2*)&qb.w); a[14] = f.x; a[15] = f.y;
    }
    int c2 = cluster2[n];
    int b1v = d_batch1[n];
    int bt = b1v > 0 ? b1v : 0;
    float* xm = d_x2max + (size_t)c2 * 16;
#pragma unroll
    for (int o = 0; o < 16; o++) {
        float r = 0.0f;
#pragma unroll
        for (int i = 0; i < 8; i++) r += xv[i] * sroot[i * 16 + o];
        float h = a[o] * inv + r + sb2[o];
        h = elu1(h);
        atomicMaxFloat(&xm[o], h);
    }
    atomicMax(&d_batch2[c2], bt);
}

// scatter_mean over graphs
__global__ void k_final(int N2) {
    int n = blockIdx.x * blockDim.x + threadIdx.x;
    if (n >= N2) return;
    int b2v = d_batch2[n];
    int b = b2v > 0 ? b2v : 0;
    float v[16];
#pragma unroll
    for (int i = 0; i < 16; i++) {
        float t = d_x2max[(size_t)n * 16 + i];
        v[i] = (t == -INFINITY) ? 0.0f : t;
    }
    float* g = d_gsum + b * 16;
    red_add_v4(g,      make_float4(v[0], v[1], v[2], v[3]));
    red_add_v4(g + 4,  make_float4(v[4], v[5], v[6], v[7]));
    red_add_v4(g + 8,  make_float4(v[8], v[9], v[10], v[11]));
    red_add_v4(g + 12, make_float4(v[12], v[13], v[14], v[15]));
    atomicAdd(&d_gcnt[b], 1);
}

// B=16 MLP head, single block
__global__ void k_mlp(const float* __restrict__ fc1w, const float* __restrict__ fc1b,
                      const float* __restrict__ fc2w, const float* __restrict__ fc2b,
                      float* __restrict__ out) {
    __shared__ float g[BGRAPH * 16];
    __shared__ float hid[BGRAPH * 64];
    int t = threadIdx.x;  // 256 threads
    if (t < BGRAPH * 16) {
        int b = t >> 4;
        int c = d_gcnt[b];
        g[t] = d_gsum[t] / (float)(c > 1 ? c : 1);
    }
    __syncthreads();
    for (int i = t; i < BGRAPH * 64; i += 256) {
        int b = i >> 6, j = i & 63;
        float s = fc1b[j];
#pragma unroll
        for (int k = 0; k < 16; k++) s += g[b * 16 + k] * fc1w[k * 64 + j];
        hid[i] = elu1(s);
    }
    __syncthreads();
    if (t < BGRAPH) {
        float s = fc2b[0];
#pragma unroll
        for (int j = 0; j < 64; j++) s += hid[t * 64 + j] * fc2w[j];
        out[t] = elu1(s);
    }
}

// ---------------- launch ----------------
extern "C" void kernel_launch(void* const* d_in, const int* in_sizes, int n_in,
                              void* d_out, int out_size) {
    const float* x        = (const float*)d_in[0];
    const int*   ei       = (const int*)d_in[1];
    const float* attr     = (const float*)d_in[2];
    const int*   batch    = (const int*)d_in[3];
    const int*   cluster1 = (const int*)d_in[4];
    const int*   cluster2 = (const int*)d_in[5];
    const float* W1       = (const float*)d_in[6];
    const float* root1    = (const float*)d_in[7];
    const float* b1       = (const float*)d_in[8];
    const float* W2       = (const float*)d_in[9];
    const float* root2    = (const float*)d_in[10];
    const float* b2       = (const float*)d_in[11];
    const float* fc1w     = (const float*)d_in[12];
    const float* fc1b     = (const float*)d_in[13];
    const float* fc2w     = (const float*)d_in[14];
    const float* fc2b     = (const float*)d_in[15];
    float* out = (float*)d_out;

    int N  = in_sizes[0] / 2;
    int E  = in_sizes[1] / 2;
    int N1 = in_sizes[5];      // cluster2 has length N1
    int N2 = N1 / 2;

    const int T = 256;
    k_init_a<<<256, T>>>(x, cluster1, N);
    k_init_b<<<256, T>>>(N1);
    k_init_c<<<128, T>>>(N2);
    k_edge1<<<(E + T - 1) / T, T>>>(ei, attr, W1, cluster1, E);
    k_node1<<<(N + T - 1) / T, T>>>(x, batch, cluster1, root1, b1, N);
    {
        int blocks = (N1 + 31) / 32;   // 8 nodes per warp, 4 warps per block
        k_xw2<<<blocks, 128>>>(W2, N1);
    }
    k_edge2<<<(2 * E + T - 1) / T, T>>>(attr, E);
    k_node2<<<(N1 + T - 1) / T, T>>>(cluster2, root2, b2, N1);
    k_final<<<(N2 + T - 1) / T, T>>>(N2);
    k_mlp<<<1, T>>>(fc1w, fc1b, fc2w, fc2b, out);
}

// round 15
// speedup vs baseline: 1.2319x; 1.0064x over previous
#include <cuda_runtime.h>
#include <cuda_fp16.h>
#include <math.h>

// Problem dims (fixed by the dataset)
#define NMAX   80000
#define N1MAX  40000
#define N2MAX  20000
#define EMAX   1280000
#define NUMK   27
#define BGRAPH 16

// ---------------- scratch (static __device__ — no allocations) ----------------
__device__ __align__(16) __half d_xw2h[(size_t)N1MAX * 512];   // 41 MB fp16 xW2 table
__device__ float4 d_pk[NMAX];            // packed (x0, x1, cluster1_bits, 0)
__device__ __align__(16) __half d_agg1h[NMAX * 8];    // fp16 level-1 aggregation
__device__ int   d_cnt1[NMAX];
__device__ float d_x1max[N1MAX * 8];
__device__ int   d_batch1[N1MAX];
__device__ __align__(16) __half d_agg2h[N1MAX * 16];  // fp16 level-2 aggregation
__device__ int   d_cnt2[N1MAX];
__device__ float d_x2max[N2MAX * 16];
__device__ int   d_batch2[N2MAX];
__device__ float d_gsum[BGRAPH * 16];
__device__ int   d_gcnt[BGRAPH];
__device__ int2  d_sd2[EMAX];    // packed (src2, dst2)

// ---------------- packed f32x2 helpers (sm_103a) ----------------
#define PACK2(d, lo, hi) \
    asm("mov.b64 %0, {%1, %2};" : "=l"(d) : "f"(lo), "f"(hi))
#define FMA2(acc, a, b) \
    asm("fma.rn.f32x2 %0, %1, %2, %3;" : "=l"(acc) : "l"(a), "l"(b), "l"(acc))

// ---------------- helpers ----------------
__device__ __forceinline__ float elu1(float v) {
    return v > 0.0f ? v : (expf(v) - 1.0f);
}

__device__ __forceinline__ void atomicMaxFloat(float* addr, float value) {
    if (value >= 0.0f)
        atomicMax((int*)addr, __float_as_int(value));
    else
        atomicMin((unsigned int*)addr, __float_as_uint(value));
}

__device__ __forceinline__ void red_add_v4(float* p, float4 v) {
    asm volatile("red.global.add.v4.f32 [%0], {%1,%2,%3,%4};"
                 :: "l"(p), "f"(v.x), "f"(v.y), "f"(v.z), "f"(v.w) : "memory");
}

// 8 halves (4 x f16x2) in ONE vector reduction
__device__ __forceinline__ void red_add_v4h2(__half* p, unsigned h0, unsigned h1,
                                             unsigned h2, unsigned h3) {
    asm volatile("red.global.add.noftz.v4.f16x2 [%0], {%1,%2,%3,%4};"
                 :: "l"(p), "r"(h0), "r"(h1), "r"(h2), "r"(h3) : "memory");
}

__device__ __forceinline__ unsigned h2u(__half2 h) { return *(unsigned*)&h; }
__device__ __forceinline__ __half2 u2h(unsigned u) { return *(__half2*)&u; }

// degree-1 open B-spline basis on 3-dim pseudo coords, K=3
__device__ __forceinline__ void basis27(float a0, float a1, float a2,
                                        float* bw, int* kk) {
    float v0 = a0 * 2.0f, v1 = a1 * 2.0f, v2 = a2 * 2.0f;
    int i0 = (int)v0; i0 = i0 < 0 ? 0 : (i0 > 1 ? 1 : i0);
    int i1 = (int)v1; i1 = i1 < 0 ? 0 : (i1 > 1 ? 1 : i1);
    int i2 = (int)v2; i2 = i2 < 0 ? 0 : (i2 > 1 ? 1 : i2);
    float f0 = v0 - (float)i0, f1 = v1 - (float)i1, f2 = v2 - (float)i2;
    float g0 = 1.0f - f0, g1 = 1.0f - f1, g2 = 1.0f - f2;
#pragma unroll
    for (int s = 0; s < 8; s++) {
        int b0 = s & 1, b1 = (s >> 1) & 1, b2 = (s >> 2) & 1;
        float w0 = b0 ? f0 : g0;
        float w1 = b1 ? f1 : g1;
        float w2 = b2 ? f2 : g2;
        bw[s] = w0 * w1 * w2;
        kk[s] = (i0 + b0) + 3 * (i1 + b1) + 9 * (i2 + b2);
    }
}

// ---------------- kernels ----------------

__global__ void k_init_a(const float* __restrict__ x, const int* __restrict__ cluster1, int N) {
    int tid = blockIdx.x * blockDim.x + threadIdx.x;
    int stride = gridDim.x * blockDim.x;
    uint4 z4 = make_uint4(0, 0, 0, 0);
    for (int i = tid; i < N; i += stride) {
        float2 xv = ((const float2*)x)[i];
        d_pk[i] = make_float4(xv.x, xv.y, __int_as_float(cluster1[i]), 0.0f);
    }
    for (int i = tid; i < N; i += stride)      ((uint4*)d_agg1h)[i] = z4;   // 8 halves/node
    for (int i = tid; i < N / 4; i += stride)  ((int4*)d_cnt1)[i] = make_int4(0, 0, 0, 0);
}

__global__ void k_init_b(int N1) {
    int tid = blockIdx.x * blockDim.x + threadIdx.x;
    int stride = gridDim.x * blockDim.x;
    uint4 z4 = make_uint4(0, 0, 0, 0);
    float4 nf4 = make_float4(-INFINITY, -INFINITY, -INFINITY, -INFINITY);
    for (int i = tid; i < N1 * 2; i += stride) ((float4*)d_x1max)[i] = nf4;
    for (int i = tid; i < N1; i += stride)     d_batch1[i] = -0x7fffffff - 1;
    for (int i = tid; i < N1 * 2; i += stride) ((uint4*)d_agg2h)[i] = z4;   // 16 halves/node
    for (int i = tid; i < N1 / 4; i += stride) ((int4*)d_cnt2)[i] = make_int4(0, 0, 0, 0);
}

__global__ void k_init_c(int N2) {
    int tid = blockIdx.x * blockDim.x + threadIdx.x;
    int stride = gridDim.x * blockDim.x;
    float4 nf4 = make_float4(-INFINITY, -INFINITY, -INFINITY, -INFINITY);
    for (int i = tid; i < N2 * 4; i += stride) ((float4*)d_x2max)[i] = nf4;
    for (int i = tid; i < N2; i += stride)     d_batch2[i] = -0x7fffffff - 1;
    for (int i = tid; i < BGRAPH * 16; i += stride) d_gsum[i] = 0.0f;
    for (int i = tid; i < BGRAPH; i += stride) d_gcnt[i] = 0;
}

// level-1 edge kernel + bookkeeping fused. W1 in smem as fp16.
// Native HFMA2 accumulation (no half<->float converts in the hot loop);
// message reduced with ONE red.v4.f16x2 (8 halves).
__global__ void __launch_bounds__(256, 4) k_edge1(
        const int* __restrict__ ei, const float* __restrict__ attr,
        const float* __restrict__ W1, const int* __restrict__ cluster1, int E) {
    __shared__ uint4 sWh[NUMK * 3];  // per k: [u 8 half][v 8 half][pad] (48B stride)
    int t = threadIdx.x;
    if (t < NUMK * 2) {
        int k = t >> 1, p = t & 1;
        const float* w = W1 + (k * 2 + p) * 8;
        __half2 h0 = __floats2half2_rn(w[0], w[1]);
        __half2 h1 = __floats2half2_rn(w[2], w[3]);
        __half2 h2 = __floats2half2_rn(w[4], w[5]);
        __half2 h3 = __floats2half2_rn(w[6], w[7]);
        uint4 q;
        q.x = h2u(h0); q.y = h2u(h1); q.z = h2u(h2); q.w = h2u(h3);
        sWh[k * 3 + p] = q;
    }
    __syncthreads();
    int e = blockIdx.x * blockDim.x + t;
    if (e >= E) return;
    int src = ei[e];
    int dst = ei[E + e];
    float4 ps = __ldg(&d_pk[src]);         // random gather #1 (x + cluster1[src])
    int d2 = __ldg(&cluster1[dst]);        // random gather #2
    d_sd2[e] = make_int2(__float_as_int(ps.z), d2);
    atomicAdd(&d_cnt1[dst], 1);
    float a0 = attr[3 * e], a1 = attr[3 * e + 1], a2 = attr[3 * e + 2];
    float bw[8]; int kk[8];
    basis27(a0, a1, a2, bw, kk);
    __half2 z = __float2half2_rn(0.0f);
    __half2 au0 = z, au1 = z, au2 = z, au3 = z;
    __half2 av0 = z, av1 = z, av2 = z, av3 = z;
#pragma unroll
    for (int s = 0; s < 8; s++) {
        uint4 qu = sWh[kk[s] * 3];
        uint4 qv = sWh[kk[s] * 3 + 1];
        __half2 bb = __float2half2_rn(bw[s]);
        au0 = __hfma2(u2h(qu.x), bb, au0);
        au1 = __hfma2(u2h(qu.y), bb, au1);
        au2 = __hfma2(u2h(qu.z), bb, au2);
        au3 = __hfma2(u2h(qu.w), bb, au3);
        av0 = __hfma2(u2h(qv.x), bb, av0);
        av1 = __hfma2(u2h(qv.y), bb, av1);
        av2 = __hfma2(u2h(qv.z), bb, av2);
        av3 = __hfma2(u2h(qv.w), bb, av3);
    }
    __half2 x0h = __float2half2_rn(ps.x);
    __half2 x1h = __float2half2_rn(ps.y);
    __half2 m0 = __hfma2(au0, x0h, __hmul2(av0, x1h));
    __half2 m1 = __hfma2(au1, x0h, __hmul2(av1, x1h));
    __half2 m2 = __hfma2(au2, x0h, __hmul2(av2, x1h));
    __half2 m3 = __hfma2(au3, x0h, __hmul2(av3, x1h));
    red_add_v4h2(d_agg1h + (size_t)dst * 8, h2u(m0), h2u(m1), h2u(m2), h2u(m3));
}

// level-1 node kernel: mean + root + bias + ELU, then seg_max pooling scatter.
// Also accumulates cnt2[c1] += cnt1[n].
__global__ void k_node1(const float* __restrict__ x, const int* __restrict__ batch,
                        const int* __restrict__ cluster1,
                        const float* __restrict__ root1, const float* __restrict__ b1,
                        int N) {
    int n = blockIdx.x * blockDim.x + threadIdx.x;
    if (n >= N) return;
    int c = d_cnt1[n];
    float inv = 1.0f / (float)(c > 1 ? c : 1);
    float x0 = x[2 * n], x1 = x[2 * n + 1];
    int c1 = cluster1[n];
    int bt = batch[n];
    uint4 q = *(const uint4*)(d_agg1h + (size_t)n * 8);
    float a[8];
    {
        float2 f0 = __half22float2(u2h(q.x));
        float2 f1 = __half22float2(u2h(q.y));
        float2 f2 = __half22float2(u2h(q.z));
        float2 f3 = __half22float2(u2h(q.w));
        a[0] = f0.x; a[1] = f0.y; a[2] = f1.x; a[3] = f1.y;
        a[4] = f2.x; a[5] = f2.y; a[6] = f3.x; a[7] = f3.y;
    }
    float* xm = d_x1max + (size_t)c1 * 8;
#pragma unroll
    for (int o = 0; o < 8; o++) {
        float h = a[o] * inv + x0 * root1[o] + x1 * root1[8 + o] + b1[o];
        h = elu1(h);
        atomicMaxFloat(&xm[o], h);
    }
    atomicMax(&d_batch1[c1], bt);
    atomicAdd(&d_cnt2[c1], c);
}

// xW2 table in fp16, padded rows: [n][32 corner slots][16 half]
// 8 nodes per warp, packed f32x2 FMA.
__global__ void __launch_bounds__(128) k_xw2(const float* __restrict__ W2, int N1) {
    __shared__ float sW[NUMK * 128];   // 13.8 KB: [k][c][o]
    int t = threadIdx.x;
    for (int i = t; i < NUMK * 128; i += 128) sW[i] = W2[i];
    __syncthreads();
    int w = (blockIdx.x * 128 + t) >> 5;
    int lane = t & 31;
    int j = lane & 7;            // output-channel pair (o = 2j, 2j+1)
    int sub = lane >> 3;         // node slot within quad
    int base = w * 8;
    if (base >= N1) return;
    unsigned long long xp[2][8];   // (xv, xv) packed per node per input channel
#pragma unroll
    for (int m = 0; m < 2; m++) {
        int node = base + m * 4 + sub;
        if (node < N1) {
            const float* xm = d_x1max + (size_t)node * 8;
#pragma unroll
            for (int c = 0; c < 8; c++) {
                float v = xm[c];
                v = (v == -INFINITY) ? 0.0f : v;   // seg_max empty-cluster fix
                PACK2(xp[m][c], v, v);
            }
        } else {
#pragma unroll
            for (int c = 0; c < 8; c++) xp[m][c] = 0ull;
        }
    }
    for (int k = 0; k < NUMK; k++) {
        unsigned long long r01[2] = {0ull, 0ull};
#pragma unroll
        for (int c = 0; c < 8; c++) {
            unsigned long long wc = *(const unsigned long long*)(sW + k * 128 + c * 16 + 2 * j);
            FMA2(r01[0], wc, xp[0][c]);
            FMA2(r01[1], wc, xp[1][c]);
        }
#pragma unroll
        for (int m = 0; m < 2; m++) {
            int node = base + m * 4 + sub;
            if (node < N1) {
                union { unsigned long long u; float2 f; } r;
                r.u = r01[m];
                *(__half2*)(d_xw2h + (size_t)node * 512 + k * 16 + 2 * j) =
                    __floats2half2_rn(r.f.x, r.f.y);
            }
        }
    }
}

// level-2 edge kernel: 2 lanes per edge, each lane owns 8 output channels.
// Native HFMA2 accumulation on the gathered fp16 rows; ONE red.v4.f16x2 per lane.
__global__ void __launch_bounds__(256, 4) k_edge2(const float* __restrict__ attr, int E) {
    int t = blockIdx.x * blockDim.x + threadIdx.x;
    int e = t >> 1;          // edge index
    int sub = t & 1;         // channel octet
    if (e >= E) return;
    int2 sd = __ldg(&d_sd2[e]);
    int s2 = sd.x;
    int d2 = sd.y;
    float a0 = attr[3 * e], a1 = attr[3 * e + 1], a2 = attr[3 * e + 2];
    float bw[8]; int kk[8];
    basis27(a0, a1, a2, bw, kk);
    const uint4* base = (const uint4*)(d_xw2h + (size_t)s2 * 512) + sub;
    uint4 q[8];
#pragma unroll
    for (int s = 0; s < 8; s++) q[s] = __ldg(base + kk[s] * 2);
    __half2 z = __float2half2_rn(0.0f);
    __half2 m0 = z, m1 = z, m2 = z, m3 = z;
#pragma unroll
    for (int s = 0; s < 8; s++) {
        __half2 bb = __float2half2_rn(bw[s]);
        m0 = __hfma2(u2h(q[s].x), bb, m0);
        m1 = __hfma2(u2h(q[s].y), bb, m1);
        m2 = __hfma2(u2h(q[s].z), bb, m2);
        m3 = __hfma2(u2h(q[s].w), bb, m3);
    }
    red_add_v4h2(d_agg2h + (size_t)d2 * 16 + sub * 8, h2u(m0), h2u(m1), h2u(m2), h2u(m3));
}

// level-2 node kernel: mean + root + bias + ELU, then seg_max pooling scatter
__global__ void __launch_bounds__(256) k_node2(const int* __restrict__ cluster2,
                        const float* __restrict__ root2, const float* __restrict__ b2,
                        int N1) {
    __shared__ float sroot[128];
    __shared__ float sb2[16];
    int t = threadIdx.x;
    if (t < 128) sroot[t] = root2[t];
    if (t < 16) sb2[t] = b2[t];
    __syncthreads();
    int n = blockIdx.x * blockDim.x + t;
    if (n >= N1) return;
    int c = d_cnt2[n];
    float inv = 1.0f / (float)(c > 1 ? c : 1);
    float xv[8];
#pragma unroll
    for (int i = 0; i < 8; i++) {
        float v = d_x1max[(size_t)n * 8 + i];
        xv[i] = (v == -INFINITY) ? 0.0f : v;
    }
    float a[16];
    {
        uint4 qa = *(const uint4*)(d_agg2h + (size_t)n * 16);
        uint4 qb = *(const uint4*)(d_agg2h + (size_t)n * 16 + 8);
        float2 f;
        f = __half22float2(u2h(qa.x)); a[0] = f.x; a[1] = f.y;
        f = __half22float2(u2h(qa.y)); a[2] = f.x; a[3] = f.y;
        f = __half22float2(u2h(qa.z)); a[4] = f.x; a[5] = f.y;
        f = __half22float2(u2h(qa.w)); a[6] = f.x; a[7] = f.y;
        f = __half22float2(u2h(qb.x)); a[8] = f.x; a[9] = f.y;
        f = __half22float2(u2h(qb.y)); a[10] = f.x; a[11] = f.y;
        f = __half22float2(u2h(qb.z)); a[12] = f.x; a[13] = f.y;
        f = __half22float2(u2h(qb.w)); a[14] = f.x; a[15] = f.y;
    }
    int c2 = cluster2[n];
    int b1v = d_batch1[n];
    int bt = b1v > 0 ? b1v : 0;
    float* xm = d_x2max + (size_t)c2 * 16;
#pragma unroll
    for (int o = 0; o < 16; o++) {
        float r = 0.0f;
#pragma unroll
        for (int i = 0; i < 8; i++) r += xv[i] * sroot[i * 16 + o];
        float h = a[o] * inv + r + sb2[o];
        h = elu1(h);
        atomicMaxFloat(&xm[o], h);
    }
    atomicMax(&d_batch2[c2], bt);
}

// scatter_mean over graphs
__global__ void k_final(int N2) {
    int n = blockIdx.x * blockDim.x + threadIdx.x;
    if (n >= N2) return;
    int b2v = d_batch2[n];
    int b = b2v > 0 ? b2v : 0;
    float v[16];
#pragma unroll
    for (int i = 0; i < 16; i++) {
        float t = d_x2max[(size_t)n * 16 + i];
        v[i] = (t == -INFINITY) ? 0.0f : t;
    }
    float* g = d_gsum + b * 16;
    red_add_v4(g,      make_float4(v[0], v[1], v[2], v[3]));
    red_add_v4(g + 4,  make_float4(v[4], v[5], v[6], v[7]));
    red_add_v4(g + 8,  make_float4(v[8], v[9], v[10], v[11]));
    red_add_v4(g + 12, make_float4(v[12], v[13], v[14], v[15]));
    atomicAdd(&d_gcnt[b], 1);
}

// B=16 MLP head, single block
__global__ void k_mlp(const float* __restrict__ fc1w, const float* __restrict__ fc1b,
                      const float* __restrict__ fc2w, const float* __restrict__ fc2b,
                      float* __restrict__ out) {
    __shared__ float g[BGRAPH * 16];
    __shared__ float hid[BGRAPH * 64];
    int t = threadIdx.x;  // 256 threads
    if (t < BGRAPH * 16) {
        int b = t >> 4;
        int c = d_gcnt[b];
        g[t] = d_gsum[t] / (float)(c > 1 ? c : 1);
    }
    __syncthreads();
    for (int i = t; i < BGRAPH * 64; i += 256) {
        int b = i >> 6, j = i & 63;
        float s = fc1b[j];
#pragma unroll
        for (int k = 0; k < 16; k++) s += g[b * 16 + k] * fc1w[k * 64 + j];
        hid[i] = elu1(s);
    }
    __syncthreads();
    if (t < BGRAPH) {
        float s = fc2b[0];
#pragma unroll
        for (int j = 0; j < 64; j++) s += hid[t * 64 + j] * fc2w[j];
        out[t] = elu1(s);
    }
}

// ---------------- launch ----------------
extern "C" void kernel_launch(void* const* d_in, const int* in_sizes, int n_in,
                              void* d_out, int out_size) {
    const float* x        = (const float*)d_in[0];
    const int*   ei       = (const int*)d_in[1];
    const float* attr     = (const float*)d_in[2];
    const int*   batch    = (const int*)d_in[3];
    const int*   cluster1 = (const int*)d_in[4];
    const int*   cluster2 = (const int*)d_in[5];
    const float* W1       = (const float*)d_in[6];
    const float* root1    = (const float*)d_in[7];
    const float* b1       = (const float*)d_in[8];
    const float* W2       = (const float*)d_in[9];
    const float* root2    = (const float*)d_in[10];
    const float* b2       = (const float*)d_in[11];
    const float* fc1w     = (const float*)d_in[12];
    const float* fc1b     = (const float*)d_in[13];
    const float* fc2w     = (const float*)d_in[14];
    const float* fc2b     = (const float*)d_in[15];
    float* out = (float*)d_out;

    int N  = in_sizes[0] / 2;
    int E  = in_sizes[1] / 2;
    int N1 = in_sizes[5];      // cluster2 has length N1
    int N2 = N1 / 2;

    const int T = 256;
    k_init_a<<<256, T>>>(x, cluster1, N);
    k_init_b<<<256, T>>>(N1);
    k_init_c<<<128, T>>>(N2);
    k_edge1<<<(E + T - 1) / T, T>>>(ei, attr, W1, cluster1, E);
    k_node1<<<(N + T - 1) / T, T>>>(x, batch, cluster1, root1, b1, N);
    {
        int blocks = (N1 + 31) / 32;   // 8 nodes per warp, 4 warps per block
        k_xw2<<<blocks, 128>>>(W2, N1);
    }
    k_edge2<<<(2 * E + T - 1) / T, T>>>(attr, E);
    k_node2<<<(N1 + T - 1) / T, T>>>(cluster2, root2, b2, N1);
    k_final<<<(N2 + T - 1) / T, T>>>(N2);
    k_mlp<<<1, T>>>(fc1w, fc1b, fc2w, fc2b, out);
}

// round 16
// speedup vs baseline: 1.2365x; 1.0037x over previous
#include <cuda_runtime.h>
#include <cuda_fp16.h>
#include <math.h>

// Problem dims (fixed by the dataset)
#define NMAX   80000
#define N1MAX  40000
#define N2MAX  20000
#define EMAX   1280000
#define NUMK   27
#define BGRAPH 16

// ---------------- scratch (static __device__ — no allocations) ----------------
__device__ __align__(16) __half d_xw2h[(size_t)N1MAX * 512];   // 41 MB fp16 xW2 table
__device__ float4 d_pk[NMAX];            // packed (x0, x1, cluster1_bits, 0)
__device__ __align__(16) __half d_agg1h[NMAX * 8];    // fp16 level-1 aggregation
__device__ int   d_cnt1[NMAX];
__device__ float d_x1max[N1MAX * 8];
__device__ int   d_batch1[N1MAX];
__device__ __align__(16) __half d_agg2fh[NMAX * 16];  // fp16 level-2 agg on FINE nodes
__device__ float d_agg2f[N1MAX * 16];                 // fp32 level-2 agg on coarse nodes
__device__ int   d_cnt2[N1MAX];
__device__ float d_x2max[N2MAX * 16];
__device__ int   d_batch2[N2MAX];
__device__ float d_gsum[BGRAPH * 16];
__device__ int   d_gcnt[BGRAPH];
__device__ int   d_s2[EMAX];     // coarse src per edge

// ---------------- packed f32x2 helpers (sm_103a) ----------------
#define PACK2(d, lo, hi) \
    asm("mov.b64 %0, {%1, %2};" : "=l"(d) : "f"(lo), "f"(hi))
#define FMA2(acc, a, b) \
    asm("fma.rn.f32x2 %0, %1, %2, %3;" : "=l"(acc) : "l"(a), "l"(b), "l"(acc))

// ---------------- helpers ----------------
__device__ __forceinline__ float elu1(float v) {
    return v > 0.0f ? v : (expf(v) - 1.0f);
}

__device__ __forceinline__ void atomicMaxFloat(float* addr, float value) {
    if (value >= 0.0f)
        atomicMax((int*)addr, __float_as_int(value));
    else
        atomicMin((unsigned int*)addr, __float_as_uint(value));
}

__device__ __forceinline__ void red_add_v4(float* p, float4 v) {
    asm volatile("red.global.add.v4.f32 [%0], {%1,%2,%3,%4};"
                 :: "l"(p), "f"(v.x), "f"(v.y), "f"(v.z), "f"(v.w) : "memory");
}

// 8 halves (4 x f16x2) in ONE vector reduction
__device__ __forceinline__ void red_add_v4h2(__half* p, unsigned h0, unsigned h1,
                                             unsigned h2, unsigned h3) {
    asm volatile("red.global.add.noftz.v4.f16x2 [%0], {%1,%2,%3,%4};"
                 :: "l"(p), "r"(h0), "r"(h1), "r"(h2), "r"(h3) : "memory");
}

__device__ __forceinline__ unsigned h2u(__half2 h) { return *(unsigned*)&h; }
__device__ __forceinline__ __half2 u2h(unsigned u) { return *(__half2*)&u; }

// degree-1 open B-spline basis on 3-dim pseudo coords, K=3
__device__ __forceinline__ void basis27(float a0, float a1, float a2,
                                        float* bw, int* kk) {
    float v0 = a0 * 2.0f, v1 = a1 * 2.0f, v2 = a2 * 2.0f;
    int i0 = (int)v0; i0 = i0 < 0 ? 0 : (i0 > 1 ? 1 : i0);
    int i1 = (int)v1; i1 = i1 < 0 ? 0 : (i1 > 1 ? 1 : i1);
    int i2 = (int)v2; i2 = i2 < 0 ? 0 : (i2 > 1 ? 1 : i2);
    float f0 = v0 - (float)i0, f1 = v1 - (float)i1, f2 = v2 - (float)i2;
    float g0 = 1.0f - f0, g1 = 1.0f - f1, g2 = 1.0f - f2;
#pragma unroll
    for (int s = 0; s < 8; s++) {
        int b0 = s & 1, b1 = (s >> 1) & 1, b2 = (s >> 2) & 1;
        float w0 = b0 ? f0 : g0;
        float w1 = b1 ? f1 : g1;
        float w2 = b2 ? f2 : g2;
        bw[s] = w0 * w1 * w2;
        kk[s] = (i0 + b0) + 3 * (i1 + b1) + 9 * (i2 + b2);
    }
}

// ---------------- kernels ----------------

__global__ void k_init_a(const float* __restrict__ x, const int* __restrict__ cluster1, int N) {
    int tid = blockIdx.x * blockDim.x + threadIdx.x;
    int stride = gridDim.x * blockDim.x;
    uint4 z4 = make_uint4(0, 0, 0, 0);
    for (int i = tid; i < N; i += stride) {
        float2 xv = ((const float2*)x)[i];
        d_pk[i] = make_float4(xv.x, xv.y, __int_as_float(cluster1[i]), 0.0f);
    }
    for (int i = tid; i < N; i += stride)      ((uint4*)d_agg1h)[i] = z4;    // 8 halves/node
    for (int i = tid; i < N * 2; i += stride)  ((uint4*)d_agg2fh)[i] = z4;   // 16 halves/node
    for (int i = tid; i < N / 4; i += stride)  ((int4*)d_cnt1)[i] = make_int4(0, 0, 0, 0);
}

__global__ void k_init_b(int N1) {
    int tid = blockIdx.x * blockDim.x + threadIdx.x;
    int stride = gridDim.x * blockDim.x;
    float4 zf4 = make_float4(0, 0, 0, 0);
    float4 nf4 = make_float4(-INFINITY, -INFINITY, -INFINITY, -INFINITY);
    for (int i = tid; i < N1 * 2; i += stride) ((float4*)d_x1max)[i] = nf4;
    for (int i = tid; i < N1; i += stride)     d_batch1[i] = -0x7fffffff - 1;
    for (int i = tid; i < N1 * 4; i += stride) ((float4*)d_agg2f)[i] = zf4;
    for (int i = tid; i < N1 / 4; i += stride) ((int4*)d_cnt2)[i] = make_int4(0, 0, 0, 0);
}

__global__ void k_init_c(int N2) {
    int tid = blockIdx.x * blockDim.x + threadIdx.x;
    int stride = gridDim.x * blockDim.x;
    float4 nf4 = make_float4(-INFINITY, -INFINITY, -INFINITY, -INFINITY);
    for (int i = tid; i < N2 * 4; i += stride) ((float4*)d_x2max)[i] = nf4;
    for (int i = tid; i < N2; i += stride)     d_batch2[i] = -0x7fffffff - 1;
    for (int i = tid; i < BGRAPH * 16; i += stride) d_gsum[i] = 0.0f;
    for (int i = tid; i < BGRAPH; i += stride) d_gcnt[i] = 0;
}

// level-1 edge kernel + bookkeeping fused. W1 in smem as fp16, HFMA2 accumulation.
// Only ONE random gather per edge now (d_pk[src], which carries cluster1[src]).
__global__ void __launch_bounds__(256, 4) k_edge1(
        const int* __restrict__ ei, const float* __restrict__ attr,
        const float* __restrict__ W1, int E) {
    __shared__ uint4 sWh[NUMK * 3];  // per k: [u 8 half][v 8 half][pad] (48B stride)
    int t = threadIdx.x;
    if (t < NUMK * 2) {
        int k = t >> 1, p = t & 1;
        const float* w = W1 + (k * 2 + p) * 8;
        __half2 h0 = __floats2half2_rn(w[0], w[1]);
        __half2 h1 = __floats2half2_rn(w[2], w[3]);
        __half2 h2 = __floats2half2_rn(w[4], w[5]);
        __half2 h3 = __floats2half2_rn(w[6], w[7]);
        uint4 q;
        q.x = h2u(h0); q.y = h2u(h1); q.z = h2u(h2); q.w = h2u(h3);
        sWh[k * 3 + p] = q;
    }
    __syncthreads();
    int e = blockIdx.x * blockDim.x + t;
    if (e >= E) return;
    int src = ei[e];
    int dst = ei[E + e];
    float4 ps = __ldg(&d_pk[src]);         // the only random gather
    d_s2[e] = __float_as_int(ps.z);
    atomicAdd(&d_cnt1[dst], 1);
    float a0 = attr[3 * e], a1 = attr[3 * e + 1], a2 = attr[3 * e + 2];
    float bw[8]; int kk[8];
    basis27(a0, a1, a2, bw, kk);
    __half2 z = __float2half2_rn(0.0f);
    __half2 au0 = z, au1 = z, au2 = z, au3 = z;
    __half2 av0 = z, av1 = z, av2 = z, av3 = z;
#pragma unroll
    for (int s = 0; s < 8; s++) {
        uint4 qu = sWh[kk[s] * 3];
        uint4 qv = sWh[kk[s] * 3 + 1];
        __half2 bb = __float2half2_rn(bw[s]);
        au0 = __hfma2(u2h(qu.x), bb, au0);
        au1 = __hfma2(u2h(qu.y), bb, au1);
        au2 = __hfma2(u2h(qu.z), bb, au2);
        au3 = __hfma2(u2h(qu.w), bb, au3);
        av0 = __hfma2(u2h(qv.x), bb, av0);
        av1 = __hfma2(u2h(qv.y), bb, av1);
        av2 = __hfma2(u2h(qv.z), bb, av2);
        av3 = __hfma2(u2h(qv.w), bb, av3);
    }
    __half2 x0h = __float2half2_rn(ps.x);
    __half2 x1h = __float2half2_rn(ps.y);
    __half2 m0 = __hfma2(au0, x0h, __hmul2(av0, x1h));
    __half2 m1 = __hfma2(au1, x0h, __hmul2(av1, x1h));
    __half2 m2 = __hfma2(au2, x0h, __hmul2(av2, x1h));
    __half2 m3 = __hfma2(au3, x0h, __hmul2(av3, x1h));
    red_add_v4h2(d_agg1h + (size_t)dst * 8, h2u(m0), h2u(m1), h2u(m2), h2u(m3));
}

// level-1 node kernel: mean + root + bias + ELU, then seg_max pooling scatter.
// Also accumulates cnt2[c1] += cnt1[n].
__global__ void k_node1(const float* __restrict__ x, const int* __restrict__ batch,
                        const int* __restrict__ cluster1,
                        const float* __restrict__ root1, const float* __restrict__ b1,
                        int N) {
    int n = blockIdx.x * blockDim.x + threadIdx.x;
    if (n >= N) return;
    int c = d_cnt1[n];
    float inv = 1.0f / (float)(c > 1 ? c : 1);
    float x0 = x[2 * n], x1 = x[2 * n + 1];
    int c1 = cluster1[n];
    int bt = batch[n];
    uint4 q = *(const uint4*)(d_agg1h + (size_t)n * 8);
    float a[8];
    {
        float2 f0 = __half22float2(u2h(q.x));
        float2 f1 = __half22float2(u2h(q.y));
        float2 f2 = __half22float2(u2h(q.z));
        float2 f3 = __half22float2(u2h(q.w));
        a[0] = f0.x; a[1] = f0.y; a[2] = f1.x; a[3] = f1.y;
        a[4] = f2.x; a[5] = f2.y; a[6] = f3.x; a[7] = f3.y;
    }
    float* xm = d_x1max + (size_t)c1 * 8;
#pragma unroll
    for (int o = 0; o < 8; o++) {
        float h = a[o] * inv + x0 * root1[o] + x1 * root1[8 + o] + b1[o];
        h = elu1(h);
        atomicMaxFloat(&xm[o], h);
    }
    atomicMax(&d_batch1[c1], bt);
    atomicAdd(&d_cnt2[c1], c);
}

// xW2 table in fp16, padded rows: [n][32 corner slots][16 half]
// 8 nodes per warp, packed f32x2 FMA.
__global__ void __launch_bounds__(128) k_xw2(const float* __restrict__ W2, int N1) {
    __shared__ float sW[NUMK * 128];   // 13.8 KB: [k][c][o]
    int t = threadIdx.x;
    for (int i = t; i < NUMK * 128; i += 128) sW[i] = W2[i];
    __syncthreads();
    int w = (blockIdx.x * 128 + t) >> 5;
    int lane = t & 31;
    int j = lane & 7;            // output-channel pair (o = 2j, 2j+1)
    int sub = lane >> 3;         // node slot within quad
    int base = w * 8;
    if (base >= N1) return;
    unsigned long long xp[2][8];   // (xv, xv) packed per node per input channel
#pragma unroll
    for (int m = 0; m < 2; m++) {
        int node = base + m * 4 + sub;
        if (node < N1) {
            const float* xm = d_x1max + (size_t)node * 8;
#pragma unroll
            for (int c = 0; c < 8; c++) {
                float v = xm[c];
                v = (v == -INFINITY) ? 0.0f : v;   // seg_max empty-cluster fix
                PACK2(xp[m][c], v, v);
            }
        } else {
#pragma unroll
            for (int c = 0; c < 8; c++) xp[m][c] = 0ull;
        }
    }
    for (int k = 0; k < NUMK; k++) {
        unsigned long long r01[2] = {0ull, 0ull};
#pragma unroll
        for (int c = 0; c < 8; c++) {
            unsigned long long wc = *(const unsigned long long*)(sW + k * 128 + c * 16 + 2 * j);
            FMA2(r01[0], wc, xp[0][c]);
            FMA2(r01[1], wc, xp[1][c]);
        }
#pragma unroll
        for (int m = 0; m < 2; m++) {
            int node = base + m * 4 + sub;
            if (node < N1) {
                union { unsigned long long u; float2 f; } r;
                r.u = r01[m];
                *(__half2*)(d_xw2h + (size_t)node * 512 + k * 16 + 2 * j) =
                    __floats2half2_rn(r.f.x, r.f.y);
            }
        }
    }
}

// level-2 edge kernel: 2 lanes per edge, each lane owns 8 output channels.
// REDs onto the FINE destination node (coalesced dst read; fold pass maps to coarse).
__global__ void __launch_bounds__(256, 4) k_edge2(
        const int* __restrict__ ei, const float* __restrict__ attr, int E) {
    int t = blockIdx.x * blockDim.x + threadIdx.x;
    int e = t >> 1;          // edge index
    int sub = t & 1;         // channel octet
    if (e >= E) return;
    int s2 = __ldg(&d_s2[e]);
    int dst = __ldg(&ei[E + e]);
    float a0 = attr[3 * e], a1 = attr[3 * e + 1], a2 = attr[3 * e + 2];
    float bw[8]; int kk[8];
    basis27(a0, a1, a2, bw, kk);
    const uint4* base = (const uint4*)(d_xw2h + (size_t)s2 * 512) + sub;
    uint4 q[8];
#pragma unroll
    for (int s = 0; s < 8; s++) q[s] = __ldg(base + kk[s] * 2);
    __half2 z = __float2half2_rn(0.0f);
    __half2 m0 = z, m1 = z, m2 = z, m3 = z;
#pragma unroll
    for (int s = 0; s < 8; s++) {
        __half2 bb = __float2half2_rn(bw[s]);
        m0 = __hfma2(u2h(q[s].x), bb, m0);
        m1 = __hfma2(u2h(q[s].y), bb, m1);
        m2 = __hfma2(u2h(q[s].z), bb, m2);
        m3 = __hfma2(u2h(q[s].w), bb, m3);
    }
    red_add_v4h2(d_agg2fh + (size_t)dst * 16 + sub * 8, h2u(m0), h2u(m1), h2u(m2), h2u(m3));
}

// fold fine-level level-2 aggregation into coarse fp32 rows
__global__ void __launch_bounds__(256) k_fold(const int* __restrict__ cluster1, int N) {
    int n = blockIdx.x * blockDim.x + threadIdx.x;
    if (n >= N) return;
    uint4 qa = *(const uint4*)(d_agg2fh + (size_t)n * 16);
    uint4 qb = *(const uint4*)(d_agg2fh + (size_t)n * 16 + 8);
    int c1 = cluster1[n];
    float* out = d_agg2f + (size_t)c1 * 16;
    float2 f0 = __half22float2(u2h(qa.x)), f1 = __half22float2(u2h(qa.y));
    float2 f2 = __half22float2(u2h(qa.z)), f3 = __half22float2(u2h(qa.w));
    float2 f4 = __half22float2(u2h(qb.x)), f5 = __half22float2(u2h(qb.y));
    float2 f6 = __half22float2(u2h(qb.z)), f7 = __half22float2(u2h(qb.w));
    red_add_v4(out,      make_float4(f0.x, f0.y, f1.x, f1.y));
    red_add_v4(out + 4,  make_float4(f2.x, f2.y, f3.x, f3.y));
    red_add_v4(out + 8,  make_float4(f4.x, f4.y, f5.x, f5.y));
    red_add_v4(out + 12, make_float4(f6.x, f6.y, f7.x, f7.y));
}

// level-2 node kernel: mean + root + bias + ELU, then seg_max pooling scatter
__global__ void __launch_bounds__(256) k_node2(const int* __restrict__ cluster2,
                        const float* __restrict__ root2, const float* __restrict__ b2,
                        int N1) {
    __shared__ float sroot[128];
    __shared__ float sb2[16];
    int t = threadIdx.x;
    if (t < 128) sroot[t] = root2[t];
    if (t < 16) sb2[t] = b2[t];
    __syncthreads();
    int n = blockIdx.x * blockDim.x + t;
    if (n >= N1) return;
    int c = d_cnt2[n];
    float inv = 1.0f / (float)(c > 1 ? c : 1);
    float xv[8];
#pragma unroll
    for (int i = 0; i < 8; i++) {
        float v = d_x1max[(size_t)n * 8 + i];
        xv[i] = (v == -INFINITY) ? 0.0f : v;
    }
    int c2 = cluster2[n];
    int b1v = d_batch1[n];
    int bt = b1v > 0 ? b1v : 0;
    float* xm = d_x2max + (size_t)c2 * 16;
#pragma unroll
    for (int o = 0; o < 16; o++) {
        float r = 0.0f;
#pragma unroll
        for (int i = 0; i < 8; i++) r += xv[i] * sroot[i * 16 + o];
        float h = d_agg2f[(size_t)n * 16 + o] * inv + r + sb2[o];
        h = elu1(h);
        atomicMaxFloat(&xm[o], h);
    }
    atomicMax(&d_batch2[c2], bt);
}

// scatter_mean over graphs
__global__ void k_final(int N2) {
    int n = blockIdx.x * blockDim.x + threadIdx.x;
    if (n >= N2) return;
    int b2v = d_batch2[n];
    int b = b2v > 0 ? b2v : 0;
    float v[16];
#pragma unroll
    for (int i = 0; i < 16; i++) {
        float t = d_x2max[(size_t)n * 16 + i];
        v[i] = (t == -INFINITY) ? 0.0f : t;
    }
    float* g = d_gsum + b * 16;
    red_add_v4(g,      make_float4(v[0], v[1], v[2], v[3]));
    red_add_v4(g + 4,  make_float4(v[4], v[5], v[6], v[7]));
    red_add_v4(g + 8,  make_float4(v[8], v[9], v[10], v[11]));
    red_add_v4(g + 12, make_float4(v[12], v[13], v[14], v[15]));
    atomicAdd(&d_gcnt[b], 1);
}

// B=16 MLP head, single block
__global__ void k_mlp(const float* __restrict__ fc1w, const float* __restrict__ fc1b,
                      const float* __restrict__ fc2w, const float* __restrict__ fc2b,
                      float* __restrict__ out) {
    __shared__ float g[BGRAPH * 16];
    __shared__ float hid[BGRAPH * 64];
    int t = threadIdx.x;  // 256 threads
    if (t < BGRAPH * 16) {
        int b = t >> 4;
        int c = d_gcnt[b];
        g[t] = d_gsum[t] / (float)(c > 1 ? c : 1);
    }
    __syncthreads();
    for (int i = t; i < BGRAPH * 64; i += 256) {
        int b = i >> 6, j = i & 63;
        float s = fc1b[j];
#pragma unroll
        for (int k = 0; k < 16; k++) s += g[b * 16 + k] * fc1w[k * 64 + j];
        hid[i] = elu1(s);
    }
    __syncthreads();
    if (t < BGRAPH) {
        float s = fc2b[0];
#pragma unroll
        for (int j = 0; j < 64; j++) s += hid[t * 64 + j] * fc2w[j];
        out[t] = elu1(s);
    }
}

// ---------------- launch ----------------
extern "C" void kernel_launch(void* const* d_in, const int* in_sizes, int n_in,
                              void* d_out, int out_size) {
    const float* x        = (const float*)d_in[0];
    const int*   ei       = (const int*)d_in[1];
    const float* attr     = (const float*)d_in[2];
    const int*   batch    = (const int*)d_in[3];
    const int*   cluster1 = (const int*)d_in[4];
    const int*   cluster2 = (const int*)d_in[5];
    const float* W1       = (const float*)d_in[6];
    const float* root1    = (const float*)d_in[7];
    const float* b1       = (const float*)d_in[8];
    const float* W2       = (const float*)d_in[9];
    const float* root2    = (const float*)d_in[10];
    const float* b2       = (const float*)d_in[11];
    const float* fc1w     = (const float*)d_in[12];
    const float* fc1b     = (const float*)d_in[13];
    const float* fc2w     = (const float*)d_in[14];
    const float* fc2b     = (const float*)d_in[15];
    float* out = (float*)d_out;

    int N  = in_sizes[0] / 2;
    int E  = in_sizes[1] / 2;
    int N1 = in_sizes[5];      // cluster2 has length N1
    int N2 = N1 / 2;

    const int T = 256;
    k_init_a<<<256, T>>>(x, cluster1, N);
    k_init_b<<<256, T>>>(N1);
    k_init_c<<<128, T>>>(N2);
    k_edge1<<<(E + T - 1) / T, T>>>(ei, attr, W1, E);
    k_node1<<<(N + T - 1) / T, T>>>(x, batch, cluster1, root1, b1, N);
    {
        int blocks = (N1 + 31) / 32;   // 8 nodes per warp, 4 warps per block
        k_xw2<<<blocks, 128>>>(W2, N1);
    }
    k_edge2<<<(2 * E + T - 1) / T, T>>>(ei, attr, E);
    k_fold<<<(N + T - 1) / T, T>>>(cluster1, N);
    k_node2<<<(N1 + T - 1) / T, T>>>(cluster2, root2, b2, N1);
    k_final<<<(N2 + T - 1) / T, T>>>(N2);
    k_mlp<<<1, T>>>(fc1w, fc1b, fc2w, fc2b, out);
}